// round 2
// baseline (speedup 1.0000x reference)
#include <cuda_runtime.h>
#include <cuda_bf16.h>

#define SEQ     4096
#define DMODEL  1024
#define DPROJ   4384
#define DINNER  2048
#define DCONVIN 2304
#define DSTATE  128
#define NH      32
#define HD      64
#define NCH     32
#define CH      128

// ---------------- scratch (static __device__, allocation-free) ----------------
__device__ float g_zx [SEQ * DPROJ];          // in_proj output [t][4384]
__device__ float g_xbc[SEQ * DCONVIN];        // conv+silu output: x[0,2048) B[2048,2176) C[2176,2304)
__device__ float g_dt [NH * SEQ];             // softplus(dt) , [h][t]
__device__ float g_L  [NH * SEQ];             // per-chunk inclusive cumsum of dt*A, [h][t]
__device__ float g_S  [NCH * NH * HD * DSTATE]; // chunk-local states
__device__ float g_H  [NCH * NH * HD * DSTATE]; // chunk initial states
__device__ float g_Y  [SEQ * DINNER];         // ssm output
__device__ float g_G  [SEQ * DINNER];         // gated normed output

__device__ __forceinline__ float bf16r(float x) {
    return __bfloat162float(__float2bfloat16(x));
}
__device__ __forceinline__ float tf32hi(float x) {
    return __uint_as_float(__float_as_uint(x) & 0xFFFFE000u);
}

#define MMA_TF32(d, a, b)                                                        \
    asm volatile("mma.sync.aligned.m16n8k8.row.col.f32.tf32.tf32.f32 "           \
                 "{%0,%1,%2,%3}, {%4,%5,%6,%7}, {%8,%9}, {%0,%1,%2,%3};"         \
                 : "+f"(d[0]), "+f"(d[1]), "+f"(d[2]), "+f"(d[3])                \
                 : "r"(__float_as_uint(a[0])), "r"(__float_as_uint(a[1])),       \
                   "r"(__float_as_uint(a[2])), "r"(__float_as_uint(a[3])),       \
                   "r"(__float_as_uint(b[0])), "r"(__float_as_uint(b[1])))

// ---------------- tensor-core NT GEMM: C[M,N] = A[M,K] * B[N,K]^T -------------
// tf32 mma with error-free split:
//   ROUNDA=1: A is rounded to bf16 first (exact in tf32), B split hi/lo (2 mma)
//   SPLITA=1: both A and B split hi/lo (3 mma, drops lo*lo ~2^-22)
template<int ROUNDA, int SPLITA>
__global__ void __launch_bounds__(256) gemm_tf32_kernel(
    const float* __restrict__ A, const float* __restrict__ B, float* __restrict__ C,
    int M, int N, int K)
{
    __shared__ float As[128 * 20];   // [row][k] stride 20 (conflict-free for frag LDS)
    __shared__ float Bs[128 * 20];   // [n][k]   stride 20

    const int bn = blockIdx.x * 128;
    const int bm = blockIdx.y * 128;
    const int tid = threadIdx.x;
    const int lane = tid & 31;
    const int wid = tid >> 5;
    const int warpM = wid >> 2;      // 0..1 -> m offset warpM*64
    const int warpN = wid & 3;       // 0..3 -> n offset warpN*32
    const int g = lane >> 2;         // 0..7
    const int tig = lane & 3;        // 0..3

    float acc[4][4][4];
#pragma unroll
    for (int mt = 0; mt < 4; mt++)
#pragma unroll
        for (int nt = 0; nt < 4; nt++)
#pragma unroll
            for (int e = 0; e < 4; e++) acc[mt][nt][e] = 0.f;

    for (int k0 = 0; k0 < K; k0 += 16) {
#pragma unroll
        for (int r = 0; r < 2; r++) {
            int qi = r * 256 + tid;
            int row = qi >> 2;            // 0..127
            int c4 = (qi & 3) * 4;        // 0,4,8,12
            float4 va = *(const float4*)(A + (size_t)(bm + row) * K + k0 + c4);
            if (ROUNDA) { va.x = bf16r(va.x); va.y = bf16r(va.y); va.z = bf16r(va.z); va.w = bf16r(va.w); }
            *(float4*)&As[row * 20 + c4] = va;
            int nn = bn + row;
            float4 vb = make_float4(0.f, 0.f, 0.f, 0.f);
            if (nn < N) vb = *(const float4*)(B + (size_t)nn * K + k0 + c4);
            *(float4*)&Bs[row * 20 + c4] = vb;
        }
        __syncthreads();

#pragma unroll
        for (int kh = 0; kh < 2; kh++) {
            const int kk0 = kh * 8;
            float ahi[4][4], alo[4][4];
#pragma unroll
            for (int mt = 0; mt < 4; mt++) {
                int r0 = warpM * 64 + mt * 16 + g;
#pragma unroll
                for (int e = 0; e < 4; e++) {
                    int rr = r0 + (e & 1) * 8;
                    int cc = kk0 + tig + (e >> 1) * 4;
                    float v = As[rr * 20 + cc];
                    if (SPLITA) {
                        float hi = tf32hi(v);
                        ahi[mt][e] = hi;
                        alo[mt][e] = tf32hi(v - hi);
                    } else {
                        ahi[mt][e] = v;   // bf16 values: exact in tf32
                    }
                }
            }
            float bhi[4][2], blo[4][2];
#pragma unroll
            for (int nt = 0; nt < 4; nt++) {
                int n0 = warpN * 32 + nt * 8 + g;
#pragma unroll
                for (int e = 0; e < 2; e++) {
                    float v = Bs[n0 * 20 + kk0 + tig + e * 4];
                    float hi = tf32hi(v);
                    bhi[nt][e] = hi;
                    blo[nt][e] = tf32hi(v - hi);
                }
            }
#pragma unroll
            for (int mt = 0; mt < 4; mt++)
#pragma unroll
                for (int nt = 0; nt < 4; nt++) {
                    MMA_TF32(acc[mt][nt], ahi[mt], bhi[nt]);
                    MMA_TF32(acc[mt][nt], ahi[mt], blo[nt]);
                    if (SPLITA) MMA_TF32(acc[mt][nt], alo[mt], bhi[nt]);
                }
        }
        __syncthreads();
    }

#pragma unroll
    for (int mt = 0; mt < 4; mt++) {
        int row = bm + warpM * 64 + mt * 16 + g;
#pragma unroll
        for (int nt = 0; nt < 4; nt++) {
            int col = bn + warpN * 32 + nt * 8 + tig * 2;
            if (col < N) {   // N even, col even => col+1 < N too
                C[(size_t)row * N + col]           = acc[mt][nt][0];
                C[(size_t)row * N + col + 1]       = acc[mt][nt][1];
                C[(size_t)(row + 8) * N + col]     = acc[mt][nt][2];
                C[(size_t)(row + 8) * N + col + 1] = acc[mt][nt][3];
            }
        }
    }
}

// ---------------- causal depthwise conv(4) + SiLU -----------------------------
__global__ void conv_silu_kernel(const float* __restrict__ cw, const float* __restrict__ cb)
{
    int c = blockIdx.x * 256 + threadIdx.x;
    int t = blockIdx.y;
    if (c >= DCONVIN) return;
    float s = cb[c];
#pragma unroll
    for (int k = 0; k < 4; k++) {
        int tt = t - 3 + k;
        if (tt >= 0) s += g_zx[(size_t)tt * DPROJ + DINNER + c] * cw[c * 4 + k];
    }
    g_xbc[(size_t)t * DCONVIN + c] = s / (1.f + expf(-s));
}

// ---------------- softplus(dt)+dt_bias, dt*A, per-chunk inclusive cumsum ------
__global__ void dtscan_kernel(const float* __restrict__ dt_bias, const float* __restrict__ A_log)
{
    int bid = blockIdx.x;
    int c = bid >> 5, h = bid & 31;
    int s = threadIdx.x;
    int t = c * CH + s;
    float raw = g_zx[(size_t)t * DPROJ + (DINNER + DINNER + 2 * DSTATE) + h] + dt_bias[h];
    float dtv = (raw > 20.f) ? raw : log1pf(expf(raw));
    float Ah = -expf(A_log[h]);
    __shared__ float sm[CH];
    sm[s] = dtv * Ah;
    g_dt[h * SEQ + t] = dtv;
    __syncthreads();
    for (int off = 1; off < CH; off <<= 1) {
        float add = (s >= off) ? sm[s - off] : 0.f;
        __syncthreads();
        sm[s] += add;
        __syncthreads();
    }
    g_L[h * SEQ + t] = sm[s];
}

// ---------------- pass 1: chunk-local states S[c,h] = sum_j w_j x_j B_j^T -----
__global__ void __launch_bounds__(256) chunkstate_kernel()
{
    int bid = blockIdx.x;
    int c = bid >> 5, h = bid & 31;
    __shared__ float xs[16][68];
    __shared__ float Bs[16][132];
    __shared__ float ws[16];
    int tid = threadIdx.x;
    int tx = tid & 15, ty = tid >> 4;   // n0 = tx*8, p0 = ty*4
    float Lend = g_L[h * SEQ + c * CH + CH - 1];
    int base = c * CH;
    float acc[4][8];
#pragma unroll
    for (int i = 0; i < 4; i++)
#pragma unroll
        for (int k = 0; k < 8; k++) acc[i][k] = 0.f;

    for (int j0 = 0; j0 < CH; j0 += 16) {
        {
            int j = tid >> 4, pq = tid & 15;
            float4 v = *(const float4*)&g_xbc[(size_t)(base + j0 + j) * DCONVIN + h * HD + pq * 4];
            *(float4*)&xs[j][pq * 4] = v;
        }
#pragma unroll
        for (int r = 0; r < 2; r++) {
            int qi = r * 256 + tid;
            int j = qi >> 5, nq = qi & 31;
            float4 v = *(const float4*)&g_xbc[(size_t)(base + j0 + j) * DCONVIN + DINNER + nq * 4];
            *(float4*)&Bs[j][nq * 4] = v;
        }
        if (tid < 16) {
            int t = base + j0 + tid;
            ws[tid] = expf(Lend - g_L[h * SEQ + t]) * g_dt[h * SEQ + t];
        }
        __syncthreads();
#pragma unroll
        for (int jj = 0; jj < 16; jj++) {
            float w = ws[jj];
            float4 xv = *(float4*)&xs[jj][ty * 4];
            float wx[4] = {w * xv.x, w * xv.y, w * xv.z, w * xv.w};
            float4 b0 = *(float4*)&Bs[jj][tx * 8];
            float4 b1 = *(float4*)&Bs[jj][tx * 8 + 4];
            float b[8] = {b0.x, b0.y, b0.z, b0.w, b1.x, b1.y, b1.z, b1.w};
#pragma unroll
            for (int i = 0; i < 4; i++)
#pragma unroll
                for (int k = 0; k < 8; k++) acc[i][k] += wx[i] * b[k];
        }
        __syncthreads();
    }
#pragma unroll
    for (int i = 0; i < 4; i++) {
        size_t row = ((size_t)(c * NH + h) * HD + ty * 4 + i) * DSTATE;
        float4 o0 = make_float4(acc[i][0], acc[i][1], acc[i][2], acc[i][3]);
        float4 o1 = make_float4(acc[i][4], acc[i][5], acc[i][6], acc[i][7]);
        *(float4*)&g_S[row + tx * 8] = o0;
        *(float4*)&g_S[row + tx * 8 + 4] = o1;
    }
}

// ---------------- pass 2: sequential 32-step scan over chunk states -----------
__global__ void scan_kernel()
{
    int idx = blockIdx.x * 256 + threadIdx.x;   // 262144 threads
    int h = idx >> 13;
    int rem = idx & 8191;
    float hcur = 0.f;
    for (int c = 0; c < NCH; c++) {
        size_t off = (size_t)(c * NH + h) * 8192 + rem;
        g_H[off] = hcur;
        hcur = expf(g_L[h * SEQ + c * CH + CH - 1]) * hcur + g_S[off];
    }
}

// ---------------- pass 3: per-(chunk,head) output ----------------------------
// Y[s,p] = sum_{j<=s} e^{Ls-Lj} dt_j (C_s.B_j) x_j[p]  +  e^{Ls} sum_n C[s,n] H[p,n]  +  D_h x[s,p]
#define K5_SMEM_FLOATS 23552
__global__ void __launch_bounds__(256) chunkout_kernel(const float* __restrict__ Dvec)
{
    extern __shared__ float smdyn[];
    float* Am  = smdyn;            // 128*132
    float* CsT = smdyn + 16896;    // 16*132 (n-major)
    float* BsT = smdyn + 19008;    // 16*132 (n-major)
    float* Xs  = smdyn + 21120;    // 16*68
    float* Hs  = smdyn + 22208;    // 16*68 (n-major)
    float* Ls  = smdyn + 23296;    // 128
    float* dts = smdyn + 23424;    // 128

    int bid = blockIdx.x;
    int c = bid >> 5, h = bid & 31;
    int tid = threadIdx.x;
    int ts = tid >> 4;   // s-dir (8 rows each)
    int tj = tid & 15;   // j-dir (stage1) / p-dir (stage2)
    int base = c * CH;

    if (tid < 128) {
        Ls[tid]  = g_L [h * SEQ + base + tid];
        dts[tid] = g_dt[h * SEQ + base + tid];
    }
    __syncthreads();

    // ---- stage 1: Am[s][j] = mask * e^{Ls-Lj} dt_j * (C_s . B_j)
    float acc[8][8];
#pragma unroll
    for (int i = 0; i < 8; i++)
#pragma unroll
        for (int k = 0; k < 8; k++) acc[i][k] = 0.f;

    for (int n0 = 0; n0 < DSTATE; n0 += 16) {
#pragma unroll
        for (int r = 0; r < 2; r++) {
            int qi = r * 256 + tid;
            int s = qi >> 2, nq = qi & 3;
            float4 vc = *(const float4*)&g_xbc[(size_t)(base + s) * DCONVIN + DINNER + DSTATE + n0 + nq * 4];
            CsT[(nq * 4 + 0) * 132 + s] = vc.x; CsT[(nq * 4 + 1) * 132 + s] = vc.y;
            CsT[(nq * 4 + 2) * 132 + s] = vc.z; CsT[(nq * 4 + 3) * 132 + s] = vc.w;
            float4 vb = *(const float4*)&g_xbc[(size_t)(base + s) * DCONVIN + DINNER + n0 + nq * 4];
            BsT[(nq * 4 + 0) * 132 + s] = vb.x; BsT[(nq * 4 + 1) * 132 + s] = vb.y;
            BsT[(nq * 4 + 2) * 132 + s] = vb.z; BsT[(nq * 4 + 3) * 132 + s] = vb.w;
        }
        __syncthreads();
#pragma unroll
        for (int nn = 0; nn < 16; nn++) {
            float4 c0 = *(float4*)&CsT[nn * 132 + ts * 8];
            float4 c1 = *(float4*)&CsT[nn * 132 + ts * 8 + 4];
            float4 b0 = *(float4*)&BsT[nn * 132 + tj * 8];
            float4 b1 = *(float4*)&BsT[nn * 132 + tj * 8 + 4];
            float cv[8] = {c0.x, c0.y, c0.z, c0.w, c1.x, c1.y, c1.z, c1.w};
            float bv[8] = {b0.x, b0.y, b0.z, b0.w, b1.x, b1.y, b1.z, b1.w};
#pragma unroll
            for (int i = 0; i < 8; i++)
#pragma unroll
                for (int k = 0; k < 8; k++) acc[i][k] += cv[i] * bv[k];
        }
        __syncthreads();
    }
#pragma unroll
    for (int i = 0; i < 8; i++) {
        int s = ts * 8 + i;
#pragma unroll
        for (int k = 0; k < 8; k++) {
            int j = tj * 8 + k;
            float w = (j <= s) ? expf(Ls[s] - Ls[j]) * dts[j] : 0.f;
            Am[s * 132 + j] = acc[i][k] * w;
        }
    }
    __syncthreads();

    // ---- stage 2+3: Yintra = Am @ X, Yinter = C @ H^T (fused loop over 128)
    float ai[8][4], ae[8][4];
#pragma unroll
    for (int i = 0; i < 8; i++)
#pragma unroll
        for (int r = 0; r < 4; r++) { ai[i][r] = 0.f; ae[i][r] = 0.f; }

    for (int k0 = 0; k0 < CH; k0 += 16) {
#pragma unroll
        for (int r = 0; r < 2; r++) {
            int qi = r * 256 + tid;
            int s = qi >> 2, nq = qi & 3;
            float4 vc = *(const float4*)&g_xbc[(size_t)(base + s) * DCONVIN + DINNER + DSTATE + k0 + nq * 4];
            CsT[(nq * 4 + 0) * 132 + s] = vc.x; CsT[(nq * 4 + 1) * 132 + s] = vc.y;
            CsT[(nq * 4 + 2) * 132 + s] = vc.z; CsT[(nq * 4 + 3) * 132 + s] = vc.w;
        }
        {
            int j = tid >> 4, pq = tid & 15;
            float4 v = *(const float4*)&g_xbc[(size_t)(base + k0 + j) * DCONVIN + h * HD + pq * 4];
            *(float4*)&Xs[j * 68 + pq * 4] = v;
        }
        {
            int p = tid >> 2, nq = tid & 3;
            float4 v = *(const float4*)&g_H[((size_t)(c * NH + h) * HD + p) * DSTATE + k0 + nq * 4];
            Hs[(nq * 4 + 0) * 68 + p] = v.x; Hs[(nq * 4 + 1) * 68 + p] = v.y;
            Hs[(nq * 4 + 2) * 68 + p] = v.z; Hs[(nq * 4 + 3) * 68 + p] = v.w;
        }
        __syncthreads();
#pragma unroll
        for (int kk = 0; kk < 16; kk++) {
            float4 xv = *(float4*)&Xs[kk * 68 + tj * 4];
            float4 hv = *(float4*)&Hs[kk * 68 + tj * 4];
#pragma unroll
            for (int i = 0; i < 8; i++) {
                float am = Am[(ts * 8 + i) * 132 + k0 + kk];
                float cv = CsT[kk * 132 + ts * 8 + i];
                ai[i][0] += am * xv.x; ai[i][1] += am * xv.y;
                ai[i][2] += am * xv.z; ai[i][3] += am * xv.w;
                ae[i][0] += cv * hv.x; ae[i][1] += cv * hv.y;
                ae[i][2] += cv * hv.z; ae[i][3] += cv * hv.w;
            }
        }
        __syncthreads();
    }

    float Dh = Dvec[h];
#pragma unroll
    for (int i = 0; i < 8; i++) {
        int s = ts * 8 + i;
        int trow = base + s;
        float es = expf(Ls[s]);
#pragma unroll
        for (int r = 0; r < 4; r++) {
            int p = tj * 4 + r;
            float xval = g_xbc[(size_t)trow * DCONVIN + h * HD + p];
            g_Y[(size_t)trow * DINNER + h * HD + p] = ai[i][r] + es * ae[i][r] + Dh * xval;
        }
    }
}

// ---------------- RMSNorm + SiLU gate ----------------------------------------
__global__ void normgate_kernel(const float* __restrict__ nw, const float* __restrict__ nb)
{
    int t = blockIdx.x;
    int tid = threadIdx.x;
    __shared__ float red[256];
    float ss = 0.f;
    for (int d = tid; d < DINNER; d += 256) {
        float v = g_Y[(size_t)t * DINNER + d];
        ss += v * v;
    }
    red[tid] = ss;
    __syncthreads();
    for (int off = 128; off > 0; off >>= 1) {
        if (tid < off) red[tid] += red[tid + off];
        __syncthreads();
    }
    float inv = rsqrtf(red[0] / (float)DINNER + 1e-6f);
    for (int d = tid; d < DINNER; d += 256) {
        float v = g_Y[(size_t)t * DINNER + d];
        float gg = v * inv * nw[d] + nb[d];
        float z = g_zx[(size_t)t * DPROJ + d];
        gg *= z / (1.f + expf(-z));
        g_G[(size_t)t * DINNER + d] = gg;
    }
}

// ---------------- launch ------------------------------------------------------
extern "C" void kernel_launch(void* const* d_in, const int* in_sizes, int n_in,
                              void* d_out, int out_size)
{
    const float* u       = (const float*)d_in[0];
    const float* W_in    = (const float*)d_in[1];
    const float* conv_w  = (const float*)d_in[2];
    const float* conv_b  = (const float*)d_in[3];
    const float* W_out   = (const float*)d_in[4];
    const float* norm_w  = (const float*)d_in[5];
    const float* norm_b  = (const float*)d_in[6];
    const float* dt_bias = (const float*)d_in[7];
    const float* A_log   = (const float*)d_in[8];
    const float* Dv      = (const float*)d_in[9];
    float* out = (float*)d_out;

    float *zx = nullptr, *G = nullptr;
    cudaGetSymbolAddress((void**)&zx, g_zx);
    cudaGetSymbolAddress((void**)&G,  g_G);

    // 1. in_proj GEMM: [4096,4384] = bf16(u) @ W_in^T  (tf32 TC, B split hi/lo)
    gemm_tf32_kernel<1, 0><<<dim3((DPROJ + 127) / 128, SEQ / 128), 256>>>(u, W_in, zx, SEQ, DPROJ, DMODEL);
    // 2. causal depthwise conv + silu on xBC
    conv_silu_kernel<<<dim3((DCONVIN + 255) / 256, SEQ), 256>>>(conv_w, conv_b);
    // 3. dt softplus + per-chunk cumsum of dt*A
    dtscan_kernel<<<NCH * NH, CH>>>(dt_bias, A_log);
    // 4. chunk-local states
    chunkstate_kernel<<<NCH * NH, 256>>>();
    // 5. inter-chunk scan
    scan_kernel<<<(NH * HD * DSTATE) / 256, 256>>>();
    // 6. per-chunk output (intra + inter + skip)
    cudaFuncSetAttribute(chunkout_kernel, cudaFuncAttributeMaxDynamicSharedMemorySize, K5_SMEM_FLOATS * 4);
    chunkout_kernel<<<NCH * NH, 256, K5_SMEM_FLOATS * 4>>>(Dv);
    // 7. RMSNorm + gate
    normgate_kernel<<<SEQ, 256>>>(norm_w, norm_b);
    // 8. out_proj GEMM: [4096,1024] = G @ W_out^T  (tf32 TC, both split hi/lo)
    gemm_tf32_kernel<0, 1><<<dim3(DMODEL / 128, SEQ / 128), 256>>>(G, W_out, out, SEQ, DMODEL, DINNER);
}

// round 5
// speedup vs baseline: 1.2368x; 1.2368x over previous
#include <cuda_runtime.h>
#include <cuda_bf16.h>
#include <cstdint>

#define SEQ     4096
#define DMODEL  1024
#define DPROJ   4384
#define DINNER  2048
#define DCONVIN 2304
#define DSTATE  128
#define NH      32
#define HD      64
#define NCH     32
#define CH      128

// ---------------- scratch (static __device__, allocation-free) ----------------
__device__ float g_zx [SEQ * DPROJ];          // in_proj output [t][4384]
__device__ float g_xbc[SEQ * DCONVIN];        // conv+silu output: x[0,2048) B[2048,2176) C[2176,2304)
__device__ float g_dt [NH * SEQ];             // softplus(dt) , [h][t]
__device__ float g_L  [NH * SEQ];             // per-chunk inclusive cumsum of dt*A, [h][t]
__device__ float g_S  [NCH * NH * HD * DSTATE]; // chunk-local states
__device__ float g_H  [NCH * NH * HD * DSTATE]; // chunk initial states
__device__ float g_Y  [SEQ * DINNER];         // ssm output

// pre-converted bf16 operands (stored as packed bf16x2 in uint32)
__device__ uint32_t g_u16[SEQ * DMODEL / 2];      // bf16(u), exact per reference
__device__ uint32_t g_Whi[DPROJ * DMODEL / 2];    // W_in hi
__device__ uint32_t g_Wlo[DPROJ * DMODEL / 2];    // W_in lo
__device__ uint32_t g_Vhi[DMODEL * DINNER / 2];   // W_out hi
__device__ uint32_t g_Vlo[DMODEL * DINNER / 2];   // W_out lo
__device__ uint32_t g_Ghi[SEQ * DINNER / 2];      // gated output hi
__device__ uint32_t g_Glo[SEQ * DINNER / 2];      // gated output lo

__device__ __forceinline__ float bf16r(float x) {
    return __bfloat162float(__float2bfloat16(x));
}
__device__ __forceinline__ uint32_t packbf2(float x, float y) {
    __nv_bfloat162 t = __floats2bfloat162_rn(x, y);
    return *(uint32_t*)&t;
}

#define MMA_BF16(d, a, b)                                                        \
    asm volatile("mma.sync.aligned.m16n8k16.row.col.f32.bf16.bf16.f32 "          \
                 "{%0,%1,%2,%3}, {%4,%5,%6,%7}, {%8,%9}, {%0,%1,%2,%3};"         \
                 : "+f"(d[0]), "+f"(d[1]), "+f"(d[2]), "+f"(d[3])                \
                 : "r"(a[0]), "r"(a[1]), "r"(a[2]), "r"(a[3]),                   \
                   "r"(b[0]), "r"(b[1]))

// ---------------- operand conversion kernels ----------------------------------
__global__ void convert_round_kernel(const float* __restrict__ src, uint32_t* __restrict__ dst, int npairs)
{
    int i = blockIdx.x * 256 + threadIdx.x;
    if (i >= npairs) return;
    float2 v = *(const float2*)(src + (size_t)i * 2);
    dst[i] = packbf2(v.x, v.y);
}
__global__ void convert_split_kernel(const float* __restrict__ src,
                                     uint32_t* __restrict__ hi, uint32_t* __restrict__ lo, int npairs)
{
    int i = blockIdx.x * 256 + threadIdx.x;
    if (i >= npairs) return;
    float2 v = *(const float2*)(src + (size_t)i * 2);
    float hx = bf16r(v.x), hy = bf16r(v.y);
    hi[i] = packbf2(hx, hy);
    lo[i] = packbf2(v.x - hx, v.y - hy);
}

// ---------------- tensor-core NT GEMM: C[M,N] = A[M,K] * B[N,K]^T -------------
// Operands pre-converted to packed bf16x2 (hi/lo planes).
//   HAS_ALO=0: C = Ahi*(Bhi+Blo)        (2 mma)  — A exact in bf16
//   HAS_ALO=1: C = Ahi*Bhi+Ahi*Blo+Alo*Bhi (3 mma, drops lo*lo ~2^-18)
// K-tile = 32 bf16 = 16 uint32. Smem row stride 20 uint32 -> conflict-free frags.
template<int HAS_ALO>
__global__ void __launch_bounds__(256) gemm_bf16s_kernel(
    const uint32_t* __restrict__ Ahi_g, const uint32_t* __restrict__ Alo_g,
    const uint32_t* __restrict__ Bhi_g, const uint32_t* __restrict__ Blo_g,
    float* __restrict__ C, int M, int N, int K)
{
    __shared__ uint32_t Ahs[128 * 20];
    __shared__ uint32_t Als[HAS_ALO ? 128 * 20 : 1];
    __shared__ uint32_t Bhs[128 * 20];
    __shared__ uint32_t Bls[128 * 20];

    const int K2 = K >> 1;               // uint32 per row
    const int bn = blockIdx.x * 128;
    const int bm = blockIdx.y * 128;
    const int tid = threadIdx.x;
    const int lane = tid & 31;
    const int wid = tid >> 5;
    const int warpM = wid >> 2;          // 0..1 -> m offset warpM*64
    const int warpN = wid & 3;           // 0..3 -> n offset warpN*32
    const int g = lane >> 2;             // 0..7
    const int tig = lane & 3;            // 0..3

    // per-thread load coords: 512 uint4 per operand tile, 2 per thread
    float acc[4][4][4];
#pragma unroll
    for (int mt = 0; mt < 4; mt++)
#pragma unroll
        for (int nt = 0; nt < 4; nt++)
#pragma unroll
            for (int e = 0; e < 4; e++) acc[mt][nt][e] = 0.f;

    for (int k0 = 0; k0 < K2; k0 += 16) {
#pragma unroll
        for (int r = 0; r < 2; r++) {
            int qi = r * 256 + tid;          // 0..511
            int row = qi >> 2;               // 0..127
            int q4 = (qi & 3) * 4;           // 0,4,8,12
            size_t ga = (size_t)(bm + row) * K2 + k0 + q4;
            *(uint4*)&Ahs[row * 20 + q4] = *(const uint4*)(Ahi_g + ga);
            if (HAS_ALO) *(uint4*)&Als[row * 20 + q4] = *(const uint4*)(Alo_g + ga);
            int nn = bn + row;
            uint4 vh = make_uint4(0, 0, 0, 0), vl = make_uint4(0, 0, 0, 0);
            if (nn < N) {
                size_t gb = (size_t)nn * K2 + k0 + q4;
                vh = *(const uint4*)(Bhi_g + gb);
                vl = *(const uint4*)(Blo_g + gb);
            }
            *(uint4*)&Bhs[row * 20 + q4] = vh;
            *(uint4*)&Bls[row * 20 + q4] = vl;
        }
        __syncthreads();

#pragma unroll
        for (int kh = 0; kh < 2; kh++) {
            const int kb = kh * 8;
            uint32_t bhi[4][2], blo[4][2];
#pragma unroll
            for (int nt = 0; nt < 4; nt++) {
                int nrow = warpN * 32 + nt * 8 + g;
                bhi[nt][0] = Bhs[nrow * 20 + kb + tig];
                bhi[nt][1] = Bhs[nrow * 20 + kb + 4 + tig];
                blo[nt][0] = Bls[nrow * 20 + kb + tig];
                blo[nt][1] = Bls[nrow * 20 + kb + 4 + tig];
            }
#pragma unroll
            for (int mt = 0; mt < 4; mt++) {
                int r0 = warpM * 64 + mt * 16 + g;
                uint32_t ah[4], al[4];
                ah[0] = Ahs[r0 * 20 + kb + tig];
                ah[1] = Ahs[(r0 + 8) * 20 + kb + tig];
                ah[2] = Ahs[r0 * 20 + kb + 4 + tig];
                ah[3] = Ahs[(r0 + 8) * 20 + kb + 4 + tig];
                if (HAS_ALO) {
                    al[0] = Als[r0 * 20 + kb + tig];
                    al[1] = Als[(r0 + 8) * 20 + kb + tig];
                    al[2] = Als[r0 * 20 + kb + 4 + tig];
                    al[3] = Als[(r0 + 8) * 20 + kb + 4 + tig];
                }
#pragma unroll
                for (int nt = 0; nt < 4; nt++) MMA_BF16(acc[mt][nt], ah, bhi[nt]);
#pragma unroll
                for (int nt = 0; nt < 4; nt++) MMA_BF16(acc[mt][nt], ah, blo[nt]);
                if (HAS_ALO) {
#pragma unroll
                    for (int nt = 0; nt < 4; nt++) MMA_BF16(acc[mt][nt], al, bhi[nt]);
                }
            }
        }
        __syncthreads();
    }

#pragma unroll
    for (int mt = 0; mt < 4; mt++) {
        int row = bm + warpM * 64 + mt * 16 + g;
#pragma unroll
        for (int nt = 0; nt < 4; nt++) {
            int col = bn + warpN * 32 + nt * 8 + tig * 2;
            if (col < N) {   // N even, col even => col+1 < N too
                C[(size_t)row * N + col]           = acc[mt][nt][0];
                C[(size_t)row * N + col + 1]       = acc[mt][nt][1];
                C[(size_t)(row + 8) * N + col]     = acc[mt][nt][2];
                C[(size_t)(row + 8) * N + col + 1] = acc[mt][nt][3];
            }
        }
    }
}

// ---------------- causal depthwise conv(4) + SiLU -----------------------------
__global__ void conv_silu_kernel(const float* __restrict__ cw, const float* __restrict__ cb)
{
    int c = blockIdx.x * 256 + threadIdx.x;
    int t = blockIdx.y;
    if (c >= DCONVIN) return;
    float s = cb[c];
#pragma unroll
    for (int k = 0; k < 4; k++) {
        int tt = t - 3 + k;
        if (tt >= 0) s += g_zx[(size_t)tt * DPROJ + DINNER + c] * cw[c * 4 + k];
    }
    g_xbc[(size_t)t * DCONVIN + c] = s / (1.f + expf(-s));
}

// ---------------- softplus(dt)+dt_bias, dt*A, per-chunk inclusive cumsum ------
__global__ void dtscan_kernel(const float* __restrict__ dt_bias, const float* __restrict__ A_log)
{
    int bid = blockIdx.x;
    int c = bid >> 5, h = bid & 31;
    int s = threadIdx.x;
    int t = c * CH + s;
    float raw = g_zx[(size_t)t * DPROJ + (DINNER + DINNER + 2 * DSTATE) + h] + dt_bias[h];
    float dtv = (raw > 20.f) ? raw : log1pf(expf(raw));
    float Ah = -expf(A_log[h]);
    __shared__ float sm[CH];
    sm[s] = dtv * Ah;
    g_dt[h * SEQ + t] = dtv;
    __syncthreads();
    for (int off = 1; off < CH; off <<= 1) {
        float add = (s >= off) ? sm[s - off] : 0.f;
        __syncthreads();
        sm[s] += add;
        __syncthreads();
    }
    g_L[h * SEQ + t] = sm[s];
}

// ---------------- pass 1: chunk-local states S[c,h] = sum_j w_j x_j B_j^T -----
__global__ void __launch_bounds__(256) chunkstate_kernel()
{
    int bid = blockIdx.x;
    int c = bid >> 5, h = bid & 31;
    __shared__ float xs[16][68];
    __shared__ float Bs[16][132];
    __shared__ float ws[16];
    int tid = threadIdx.x;
    int tx = tid & 15, ty = tid >> 4;   // n0 = tx*8, p0 = ty*4
    float Lend = g_L[h * SEQ + c * CH + CH - 1];
    int base = c * CH;
    float acc[4][8];
#pragma unroll
    for (int i = 0; i < 4; i++)
#pragma unroll
        for (int k = 0; k < 8; k++) acc[i][k] = 0.f;

    for (int j0 = 0; j0 < CH; j0 += 16) {
        {
            int j = tid >> 4, pq = tid & 15;
            float4 v = *(const float4*)&g_xbc[(size_t)(base + j0 + j) * DCONVIN + h * HD + pq * 4];
            *(float4*)&xs[j][pq * 4] = v;
        }
#pragma unroll
        for (int r = 0; r < 2; r++) {
            int qi = r * 256 + tid;
            int j = qi >> 5, nq = qi & 31;
            float4 v = *(const float4*)&g_xbc[(size_t)(base + j0 + j) * DCONVIN + DINNER + nq * 4];
            *(float4*)&Bs[j][nq * 4] = v;
        }
        if (tid < 16) {
            int t = base + j0 + tid;
            ws[tid] = expf(Lend - g_L[h * SEQ + t]) * g_dt[h * SEQ + t];
        }
        __syncthreads();
#pragma unroll
        for (int jj = 0; jj < 16; jj++) {
            float w = ws[jj];
            float4 xv = *(float4*)&xs[jj][ty * 4];
            float wx[4] = {w * xv.x, w * xv.y, w * xv.z, w * xv.w};
            float4 b0 = *(float4*)&Bs[jj][tx * 8];
            float4 b1 = *(float4*)&Bs[jj][tx * 8 + 4];
            float b[8] = {b0.x, b0.y, b0.z, b0.w, b1.x, b1.y, b1.z, b1.w};
#pragma unroll
            for (int i = 0; i < 4; i++)
#pragma unroll
                for (int k = 0; k < 8; k++) acc[i][k] += wx[i] * b[k];
        }
        __syncthreads();
    }
#pragma unroll
    for (int i = 0; i < 4; i++) {
        size_t row = ((size_t)(c * NH + h) * HD + ty * 4 + i) * DSTATE;
        float4 o0 = make_float4(acc[i][0], acc[i][1], acc[i][2], acc[i][3]);
        float4 o1 = make_float4(acc[i][4], acc[i][5], acc[i][6], acc[i][7]);
        *(float4*)&g_S[row + tx * 8] = o0;
        *(float4*)&g_S[row + tx * 8 + 4] = o1;
    }
}

// ---------------- pass 2: sequential 32-step scan over chunk states -----------
__global__ void scan_kernel()
{
    int idx = blockIdx.x * 256 + threadIdx.x;   // 262144 threads
    int h = idx >> 13;
    int rem = idx & 8191;
    float hcur = 0.f;
    for (int c = 0; c < NCH; c++) {
        size_t off = (size_t)(c * NH + h) * 8192 + rem;
        g_H[off] = hcur;
        hcur = expf(g_L[h * SEQ + c * CH + CH - 1]) * hcur + g_S[off];
    }
}

// ---------------- pass 3: per-(chunk,head) output ----------------------------
// Y[s,p] = sum_{j<=s} e^{Ls-Lj} dt_j (C_s.B_j) x_j[p]  +  e^{Ls} sum_n C[s,n] H[p,n]  +  D_h x[s,p]
#define K5_SMEM_FLOATS 23552
__global__ void __launch_bounds__(256) chunkout_kernel(const float* __restrict__ Dvec)
{
    extern __shared__ float smdyn[];
    float* Am  = smdyn;            // 128*132
    float* CsT = smdyn + 16896;    // 16*132 (n-major)
    float* BsT = smdyn + 19008;    // 16*132 (n-major)
    float* Xs  = smdyn + 21120;    // 16*68
    float* Hs  = smdyn + 22208;    // 16*68 (n-major)
    float* Ls  = smdyn + 23296;    // 128
    float* dts = smdyn + 23424;    // 128

    int bid = blockIdx.x;
    int c = bid >> 5, h = bid & 31;
    int tid = threadIdx.x;
    int ts = tid >> 4;   // s-dir (8 rows each)
    int tj = tid & 15;   // j-dir (stage1) / p-dir (stage2)
    int base = c * CH;

    if (tid < 128) {
        Ls[tid]  = g_L [h * SEQ + base + tid];
        dts[tid] = g_dt[h * SEQ + base + tid];
    }
    __syncthreads();

    // ---- stage 1: Am[s][j] = mask * e^{Ls-Lj} dt_j * (C_s . B_j)
    float acc[8][8];
#pragma unroll
    for (int i = 0; i < 8; i++)
#pragma unroll
        for (int k = 0; k < 8; k++) acc[i][k] = 0.f;

    for (int n0 = 0; n0 < DSTATE; n0 += 16) {
#pragma unroll
        for (int r = 0; r < 2; r++) {
            int qi = r * 256 + tid;
            int s = qi >> 2, nq = qi & 3;
            float4 vc = *(const float4*)&g_xbc[(size_t)(base + s) * DCONVIN + DINNER + DSTATE + n0 + nq * 4];
            CsT[(nq * 4 + 0) * 132 + s] = vc.x; CsT[(nq * 4 + 1) * 132 + s] = vc.y;
            CsT[(nq * 4 + 2) * 132 + s] = vc.z; CsT[(nq * 4 + 3) * 132 + s] = vc.w;
            float4 vb = *(const float4*)&g_xbc[(size_t)(base + s) * DCONVIN + DINNER + n0 + nq * 4];
            BsT[(nq * 4 + 0) * 132 + s] = vb.x; BsT[(nq * 4 + 1) * 132 + s] = vb.y;
            BsT[(nq * 4 + 2) * 132 + s] = vb.z; BsT[(nq * 4 + 3) * 132 + s] = vb.w;
        }
        __syncthreads();
#pragma unroll
        for (int nn = 0; nn < 16; nn++) {
            float4 c0 = *(float4*)&CsT[nn * 132 + ts * 8];
            float4 c1 = *(float4*)&CsT[nn * 132 + ts * 8 + 4];
            float4 b0 = *(float4*)&BsT[nn * 132 + tj * 8];
            float4 b1 = *(float4*)&BsT[nn * 132 + tj * 8 + 4];
            float cv[8] = {c0.x, c0.y, c0.z, c0.w, c1.x, c1.y, c1.z, c1.w};
            float bv[8] = {b0.x, b0.y, b0.z, b0.w, b1.x, b1.y, b1.z, b1.w};
#pragma unroll
            for (int i = 0; i < 8; i++)
#pragma unroll
                for (int k = 0; k < 8; k++) acc[i][k] += cv[i] * bv[k];
        }
        __syncthreads();
    }
#pragma unroll
    for (int i = 0; i < 8; i++) {
        int s = ts * 8 + i;
#pragma unroll
        for (int k = 0; k < 8; k++) {
            int j = tj * 8 + k;
            float w = (j <= s) ? expf(Ls[s] - Ls[j]) * dts[j] : 0.f;
            Am[s * 132 + j] = acc[i][k] * w;
        }
    }
    __syncthreads();

    // ---- stage 2+3: Yintra = Am @ X, Yinter = C @ H^T (fused loop over 128)
    float ai[8][4], ae[8][4];
#pragma unroll
    for (int i = 0; i < 8; i++)
#pragma unroll
        for (int r = 0; r < 4; r++) { ai[i][r] = 0.f; ae[i][r] = 0.f; }

    for (int k0 = 0; k0 < CH; k0 += 16) {
#pragma unroll
        for (int r = 0; r < 2; r++) {
            int qi = r * 256 + tid;
            int s = qi >> 2, nq = qi & 3;
            float4 vc = *(const float4*)&g_xbc[(size_t)(base + s) * DCONVIN + DINNER + DSTATE + k0 + nq * 4];
            CsT[(nq * 4 + 0) * 132 + s] = vc.x; CsT[(nq * 4 + 1) * 132 + s] = vc.y;
            CsT[(nq * 4 + 2) * 132 + s] = vc.z; CsT[(nq * 4 + 3) * 132 + s] = vc.w;
        }
        {
            int j = tid >> 4, pq = tid & 15;
            float4 v = *(const float4*)&g_xbc[(size_t)(base + k0 + j) * DCONVIN + h * HD + pq * 4];
            *(float4*)&Xs[j * 68 + pq * 4] = v;
        }
        {
            int p = tid >> 2, nq = tid & 3;
            float4 v = *(const float4*)&g_H[((size_t)(c * NH + h) * HD + p) * DSTATE + k0 + nq * 4];
            Hs[(nq * 4 + 0) * 68 + p] = v.x; Hs[(nq * 4 + 1) * 68 + p] = v.y;
            Hs[(nq * 4 + 2) * 68 + p] = v.z; Hs[(nq * 4 + 3) * 68 + p] = v.w;
        }
        __syncthreads();
#pragma unroll
        for (int kk = 0; kk < 16; kk++) {
            float4 xv = *(float4*)&Xs[kk * 68 + tj * 4];
            float4 hv = *(float4*)&Hs[kk * 68 + tj * 4];
#pragma unroll
            for (int i = 0; i < 8; i++) {
                float am = Am[(ts * 8 + i) * 132 + k0 + kk];
                float cv = CsT[kk * 132 + ts * 8 + i];
                ai[i][0] += am * xv.x; ai[i][1] += am * xv.y;
                ai[i][2] += am * xv.z; ai[i][3] += am * xv.w;
                ae[i][0] += cv * hv.x; ae[i][1] += cv * hv.y;
                ae[i][2] += cv * hv.z; ae[i][3] += cv * hv.w;
            }
        }
        __syncthreads();
    }

    float Dh = Dvec[h];
#pragma unroll
    for (int i = 0; i < 8; i++) {
        int s = ts * 8 + i;
        int trow = base + s;
        float es = expf(Ls[s]);
#pragma unroll
        for (int r = 0; r < 4; r++) {
            int p = tj * 4 + r;
            float xval = g_xbc[(size_t)trow * DCONVIN + h * HD + p];
            g_Y[(size_t)trow * DINNER + h * HD + p] = ai[i][r] + es * ae[i][r] + Dh * xval;
        }
    }
}

// ---------------- RMSNorm + SiLU gate -> split bf16 ---------------------------
__global__ void normgate_kernel(const float* __restrict__ nw, const float* __restrict__ nb)
{
    int t = blockIdx.x;
    int tid = threadIdx.x;
    __shared__ float red[256];
    float ss = 0.f;
    for (int d = tid; d < DINNER; d += 256) {
        float v = g_Y[(size_t)t * DINNER + d];
        ss += v * v;
    }
    red[tid] = ss;
    __syncthreads();
    for (int off = 128; off > 0; off >>= 1) {
        if (tid < off) red[tid] += red[tid + off];
        __syncthreads();
    }
    float inv = rsqrtf(red[0] / (float)DINNER + 1e-6f);
    for (int d = tid * 2; d < DINNER; d += 512) {
        float v0 = g_Y[(size_t)t * DINNER + d];
        float v1 = g_Y[(size_t)t * DINNER + d + 1];
        float g0 = v0 * inv * nw[d] + nb[d];
        float g1 = v1 * inv * nw[d + 1] + nb[d + 1];
        float z0 = g_zx[(size_t)t * DPROJ + d];
        float z1 = g_zx[(size_t)t * DPROJ + d + 1];
        g0 *= z0 / (1.f + expf(-z0));
        g1 *= z1 / (1.f + expf(-z1));
        float h0 = bf16r(g0), h1 = bf16r(g1);
        size_t pi = ((size_t)t * DINNER + d) >> 1;
        g_Ghi[pi] = packbf2(h0, h1);
        g_Glo[pi] = packbf2(g0 - h0, g1 - h1);
    }
}

// ---------------- launch ------------------------------------------------------
extern "C" void kernel_launch(void* const* d_in, const int* in_sizes, int n_in,
                              void* d_out, int out_size)
{
    const float* u       = (const float*)d_in[0];
    const float* W_in    = (const float*)d_in[1];
    const float* conv_w  = (const float*)d_in[2];
    const float* conv_b  = (const float*)d_in[3];
    const float* W_out   = (const float*)d_in[4];
    const float* norm_w  = (const float*)d_in[5];
    const float* norm_b  = (const float*)d_in[6];
    const float* dt_bias = (const float*)d_in[7];
    const float* A_log   = (const float*)d_in[8];
    const float* Dv      = (const float*)d_in[9];
    float* out = (float*)d_out;

    float *zx = nullptr;
    uint32_t *u16, *Whi, *Wlo, *Vhi, *Vlo, *Ghi, *Glo;
    cudaGetSymbolAddress((void**)&zx,  g_zx);
    cudaGetSymbolAddress((void**)&u16, g_u16);
    cudaGetSymbolAddress((void**)&Whi, g_Whi);
    cudaGetSymbolAddress((void**)&Wlo, g_Wlo);
    cudaGetSymbolAddress((void**)&Vhi, g_Vhi);
    cudaGetSymbolAddress((void**)&Vlo, g_Vlo);
    cudaGetSymbolAddress((void**)&Ghi, g_Ghi);
    cudaGetSymbolAddress((void**)&Glo, g_Glo);

    // 0. pre-convert operands to bf16 (u exact-round; weights hi/lo split)
    {
        int np;
        np = SEQ * DMODEL / 2;
        convert_round_kernel<<<(np + 255) / 256, 256>>>(u, u16, np);
        np = DPROJ * DMODEL / 2;
        convert_split_kernel<<<(np + 255) / 256, 256>>>(W_in, Whi, Wlo, np);
        np = DMODEL * DINNER / 2;
        convert_split_kernel<<<(np + 255) / 256, 256>>>(W_out, Vhi, Vlo, np);
    }
    // 1. in_proj GEMM: [4096,4384] = bf16(u) @ W_in^T  (bf16 TC, 2 mma)
    gemm_bf16s_kernel<0><<<dim3((DPROJ + 127) / 128, SEQ / 128), 256>>>(
        u16, nullptr, Whi, Wlo, zx, SEQ, DPROJ, DMODEL);
    // 2. causal depthwise conv + silu on xBC
    conv_silu_kernel<<<dim3((DCONVIN + 255) / 256, SEQ), 256>>>(conv_w, conv_b);
    // 3. dt softplus + per-chunk cumsum of dt*A
    dtscan_kernel<<<NCH * NH, CH>>>(dt_bias, A_log);
    // 4. chunk-local states
    chunkstate_kernel<<<NCH * NH, 256>>>();
    // 5. inter-chunk scan
    scan_kernel<<<(NH * HD * DSTATE) / 256, 256>>>();
    // 6. per-chunk output (intra + inter + skip)
    cudaFuncSetAttribute(chunkout_kernel, cudaFuncAttributeMaxDynamicSharedMemorySize, K5_SMEM_FLOATS * 4);
    chunkout_kernel<<<NCH * NH, 256, K5_SMEM_FLOATS * 4>>>(Dv);
    // 7. RMSNorm + gate -> split bf16
    normgate_kernel<<<SEQ, 256>>>(norm_w, norm_b);
    // 8. out_proj GEMM: [4096,1024] = G @ W_out^T  (bf16 TC, 3 mma)
    gemm_bf16s_kernel<1><<<dim3(DMODEL / 128, SEQ / 128), 256>>>(
        Ghi, Glo, Vhi, Vlo, out, SEQ, DMODEL, DINNER);
}

// round 8
// speedup vs baseline: 1.4851x; 1.2008x over previous
#include <cuda_runtime.h>
#include <cuda_bf16.h>
#include <cstdint>

#define SEQ     4096
#define DMODEL  1024
#define DPROJ   4384
#define DINNER  2048
#define DCONVIN 2304
#define DSTATE  128
#define NH      32
#define HD      64
#define NCH     32
#define CH      128

// ---------------- scratch (static __device__, allocation-free) ----------------
__device__ float g_zx [SEQ * DPROJ];          // in_proj output [t][4384]
__device__ float g_xbc[SEQ * DCONVIN];        // conv+silu: x[0,2048) B[2048,2176) C[2176,2304)
__device__ float g_dt [NH * SEQ];             // softplus(dt), [h][t]
__device__ float g_L  [NH * SEQ];             // per-chunk inclusive cumsum of dt*A, [h][t]
__device__ float g_S  [NCH * NH * HD * DSTATE]; // chunk-local states
__device__ float g_Y  [SEQ * DINNER];         // ssm output
__device__ float g_Gram[NCH * CH * CH];       // per-chunk C.B^T gram (head-independent)
__device__ float g_Inter[NCH * CH * DINNER];  // per-chunk inter-term C @ Hcat^T

// pre-converted bf16 operands (packed bf16x2 in uint32)
__device__ uint32_t g_u16[SEQ * DMODEL / 2];
__device__ uint32_t g_Whi[DPROJ * DMODEL / 2];
__device__ uint32_t g_Wlo[DPROJ * DMODEL / 2];
__device__ uint32_t g_Vhi[DMODEL * DINNER / 2];
__device__ uint32_t g_Vlo[DMODEL * DINNER / 2];
__device__ uint32_t g_Ghi[SEQ * DINNER / 2];
__device__ uint32_t g_Glo[SEQ * DINNER / 2];
__device__ uint32_t g_Hhi[NCH * DINNER * DSTATE / 2];  // chunk-initial states, split bf16
__device__ uint32_t g_Hlo[NCH * DINNER * DSTATE / 2];  // rows: c*2048 + h*64+p, cols: n pairs
__device__ uint32_t g_Chi[SEQ * DSTATE / 2];           // C block split, rows t, cols n pairs
__device__ uint32_t g_Clo[SEQ * DSTATE / 2];

__device__ __forceinline__ float bf16r(float x) {
    return __bfloat162float(__float2bfloat16(x));
}
__device__ __forceinline__ uint32_t packbf2(float x, float y) {
    __nv_bfloat162 t = __floats2bfloat162_rn(x, y);
    return *(uint32_t*)&t;
}
__device__ __forceinline__ void cp16(void* sdst, const void* gsrc, int sz) {
    uint32_t sa = (uint32_t)__cvta_generic_to_shared(sdst);
    asm volatile("cp.async.cg.shared.global [%0], [%1], 16, %2;" :: "r"(sa), "l"(gsrc), "r"(sz));
}

#define MMA_BF16(d, a, b)                                                        \
    asm volatile("mma.sync.aligned.m16n8k16.row.col.f32.bf16.bf16.f32 "          \
                 "{%0,%1,%2,%3}, {%4,%5,%6,%7}, {%8,%9}, {%0,%1,%2,%3};"         \
                 : "+f"(d[0]), "+f"(d[1]), "+f"(d[2]), "+f"(d[3])                \
                 : "r"(a[0]), "r"(a[1]), "r"(a[2]), "r"(a[3]),                   \
                   "r"(b[0]), "r"(b[1]))

// ---------------- operand conversion kernels ----------------------------------
__global__ void convert_round_kernel(const float* __restrict__ src, uint32_t* __restrict__ dst, int npairs)
{
    int i = blockIdx.x * 256 + threadIdx.x;
    if (i >= npairs) return;
    float2 v = *(const float2*)(src + (size_t)i * 2);
    dst[i] = packbf2(v.x, v.y);
}
__global__ void convert_split_kernel(const float* __restrict__ src,
                                     uint32_t* __restrict__ hi, uint32_t* __restrict__ lo, int npairs)
{
    int i = blockIdx.x * 256 + threadIdx.x;
    if (i >= npairs) return;
    float2 v = *(const float2*)(src + (size_t)i * 2);
    float hx = bf16r(v.x), hy = bf16r(v.y);
    hi[i] = packbf2(hx, hy);
    lo[i] = packbf2(v.x - hx, v.y - hy);
}

// ---------------- tensor-core NT GEMM with 2-stage cp.async pipeline ----------
// C[M,N] = A[M,K] * B[N,K]^T, operands pre-split bf16 hi/lo planes.
//   HAS_ALO=0: 2 mma (A exact);  HAS_ALO=1: 3 mma (drop lo*lo)
//   CHUNKZ=1: batched over blockIdx.z with fixed per-chunk strides (inter GEMM)
template<int HAS_ALO, int CHUNKZ = 0>
__global__ void __launch_bounds__(256) gemm_bf16s_kernel(
    const uint32_t* __restrict__ Ahi_g, const uint32_t* __restrict__ Alo_g,
    const uint32_t* __restrict__ Bhi_g, const uint32_t* __restrict__ Blo_g,
    float* __restrict__ C, int M, int N, int K)
{
    extern __shared__ uint32_t smem[];
    uint32_t* Ahs = smem;                                   // 2*2560
    uint32_t* Als = smem + 5120;                            // 2*2560 if HAS_ALO
    uint32_t* Bhs = smem + 5120 + (HAS_ALO ? 5120 : 0);     // 2*2560
    uint32_t* Bls = Bhs + 5120;                             // 2*2560

    if (CHUNKZ) {
        size_t cz = blockIdx.z;
        Ahi_g += cz * (size_t)CH * (DSTATE / 2);            // 128 rows of 64 u32
        if (HAS_ALO) Alo_g += cz * (size_t)CH * (DSTATE / 2);
        Bhi_g += cz * (size_t)DINNER * (DSTATE / 2);        // 2048 rows of 64 u32
        Blo_g += cz * (size_t)DINNER * (DSTATE / 2);
        C     += cz * (size_t)CH * DINNER;
    }

    const int K2 = K >> 1;
    const int KT = K2 >> 4;
    const int bn = blockIdx.x * 128;
    const int bm = blockIdx.y * 128;
    const int tid = threadIdx.x;
    const int lane = tid & 31;
    const int wid = tid >> 5;
    const int warpM = wid >> 2;
    const int warpN = wid & 3;
    const int g = lane >> 2;
    const int tig = lane & 3;

    auto issue = [&](int kt, int buf) {
        int k0 = kt * 16;
        int bo = buf * 2560;
#pragma unroll
        for (int r = 0; r < 2; r++) {
            int qi = r * 256 + tid;
            int row = qi >> 2;
            int q4 = (qi & 3) * 4;
            size_t ga = (size_t)(bm + row) * K2 + k0 + q4;
            cp16(&Ahs[bo + row * 20 + q4], Ahi_g + ga, 16);
            if (HAS_ALO) cp16(&Als[bo + row * 20 + q4], Alo_g + ga, 16);
            int nn = bn + row;
            int sz = (nn < N) ? 16 : 0;
            size_t gb = (size_t)((nn < N) ? nn : 0) * K2 + k0 + q4;
            cp16(&Bhs[bo + row * 20 + q4], Bhi_g + gb, sz);
            cp16(&Bls[bo + row * 20 + q4], Blo_g + gb, sz);
        }
        asm volatile("cp.async.commit_group;" ::: "memory");
    };

    float acc[4][4][4];
#pragma unroll
    for (int mt = 0; mt < 4; mt++)
#pragma unroll
        for (int nt = 0; nt < 4; nt++)
#pragma unroll
            for (int e = 0; e < 4; e++) acc[mt][nt][e] = 0.f;

    issue(0, 0);

    for (int kt = 0; kt < KT; kt++) {
        int buf = kt & 1;
        if (kt + 1 < KT) {
            issue(kt + 1, buf ^ 1);
            asm volatile("cp.async.wait_group 1;" ::: "memory");
        } else {
            asm volatile("cp.async.wait_group 0;" ::: "memory");
        }
        __syncthreads();

        const int bo = buf * 2560;
#pragma unroll
        for (int kh = 0; kh < 2; kh++) {
            const int kb = kh * 8;
            uint32_t bhi[4][2], blo[4][2];
#pragma unroll
            for (int nt = 0; nt < 4; nt++) {
                int nrow = warpN * 32 + nt * 8 + g;
                bhi[nt][0] = Bhs[bo + nrow * 20 + kb + tig];
                bhi[nt][1] = Bhs[bo + nrow * 20 + kb + 4 + tig];
                blo[nt][0] = Bls[bo + nrow * 20 + kb + tig];
                blo[nt][1] = Bls[bo + nrow * 20 + kb + 4 + tig];
            }
#pragma unroll
            for (int mt = 0; mt < 4; mt++) {
                int r0 = warpM * 64 + mt * 16 + g;
                uint32_t ah[4], al[4];
                ah[0] = Ahs[bo + r0 * 20 + kb + tig];
                ah[1] = Ahs[bo + (r0 + 8) * 20 + kb + tig];
                ah[2] = Ahs[bo + r0 * 20 + kb + 4 + tig];
                ah[3] = Ahs[bo + (r0 + 8) * 20 + kb + 4 + tig];
                if (HAS_ALO) {
                    al[0] = Als[bo + r0 * 20 + kb + tig];
                    al[1] = Als[bo + (r0 + 8) * 20 + kb + tig];
                    al[2] = Als[bo + r0 * 20 + kb + 4 + tig];
                    al[3] = Als[bo + (r0 + 8) * 20 + kb + 4 + tig];
                }
#pragma unroll
                for (int nt = 0; nt < 4; nt++) MMA_BF16(acc[mt][nt], ah, bhi[nt]);
#pragma unroll
                for (int nt = 0; nt < 4; nt++) MMA_BF16(acc[mt][nt], ah, blo[nt]);
                if (HAS_ALO) {
#pragma unroll
                    for (int nt = 0; nt < 4; nt++) MMA_BF16(acc[mt][nt], al, bhi[nt]);
                }
            }
        }
        __syncthreads();
    }

#pragma unroll
    for (int mt = 0; mt < 4; mt++) {
        int row = bm + warpM * 64 + mt * 16 + g;
#pragma unroll
        for (int nt = 0; nt < 4; nt++) {
            int col = bn + warpN * 32 + nt * 8 + tig * 2;
            if (col < N) {
                C[(size_t)row * N + col]           = acc[mt][nt][0];
                C[(size_t)row * N + col + 1]       = acc[mt][nt][1];
                C[(size_t)(row + 8) * N + col]     = acc[mt][nt][2];
                C[(size_t)(row + 8) * N + col + 1] = acc[mt][nt][3];
            }
        }
    }
}

// ---------------- causal depthwise conv(4) + SiLU -----------------------------
__global__ void conv_silu_kernel(const float* __restrict__ cw, const float* __restrict__ cb)
{
    int c = blockIdx.x * 256 + threadIdx.x;
    int t = blockIdx.y;
    if (c >= DCONVIN) return;
    float s = cb[c];
#pragma unroll
    for (int k = 0; k < 4; k++) {
        int tt = t - 3 + k;
        if (tt >= 0) s += g_zx[(size_t)tt * DPROJ + DINNER + c] * cw[c * 4 + k];
    }
    g_xbc[(size_t)t * DCONVIN + c] = s / (1.f + expf(-s));
}

// ---------------- softplus(dt)+dt_bias, dt*A, per-chunk inclusive cumsum ------
__global__ void dtscan_kernel(const float* __restrict__ dt_bias, const float* __restrict__ A_log)
{
    int bid = blockIdx.x;
    int c = bid >> 5, h = bid & 31;
    int s = threadIdx.x;
    int t = c * CH + s;
    float raw = g_zx[(size_t)t * DPROJ + (DINNER + DINNER + 2 * DSTATE) + h] + dt_bias[h];
    float dtv = (raw > 20.f) ? raw : log1pf(expf(raw));
    float Ah = -expf(A_log[h]);
    __shared__ float sm[CH];
    sm[s] = dtv * Ah;
    g_dt[h * SEQ + t] = dtv;
    __syncthreads();
    for (int off = 1; off < CH; off <<= 1) {
        float add = (s >= off) ? sm[s - off] : 0.f;
        __syncthreads();
        sm[s] += add;
        __syncthreads();
    }
    g_L[h * SEQ + t] = sm[s];
}

// ---------------- gram: G[c][s][j] = C_s . B_j (head-independent, NGROUPS=1) --
__global__ void __launch_bounds__(256) gram_kernel()
{
    int c = blockIdx.x;
    __shared__ float CsT[16 * 132];
    __shared__ float BsT[16 * 132];
    int tid = threadIdx.x;
    int ts = tid >> 4, tj = tid & 15;
    int base = c * CH;

    float acc[8][8];
#pragma unroll
    for (int i = 0; i < 8; i++)
#pragma unroll
        for (int k = 0; k < 8; k++) acc[i][k] = 0.f;

    for (int n0 = 0; n0 < DSTATE; n0 += 16) {
#pragma unroll
        for (int r = 0; r < 2; r++) {
            int qi = r * 256 + tid;
            int s = qi >> 2, nq = qi & 3;
            float4 vc = *(const float4*)&g_xbc[(size_t)(base + s) * DCONVIN + DINNER + DSTATE + n0 + nq * 4];
            CsT[(nq * 4 + 0) * 132 + s] = vc.x; CsT[(nq * 4 + 1) * 132 + s] = vc.y;
            CsT[(nq * 4 + 2) * 132 + s] = vc.z; CsT[(nq * 4 + 3) * 132 + s] = vc.w;
            float4 vb = *(const float4*)&g_xbc[(size_t)(base + s) * DCONVIN + DINNER + n0 + nq * 4];
            BsT[(nq * 4 + 0) * 132 + s] = vb.x; BsT[(nq * 4 + 1) * 132 + s] = vb.y;
            BsT[(nq * 4 + 2) * 132 + s] = vb.z; BsT[(nq * 4 + 3) * 132 + s] = vb.w;
        }
        __syncthreads();
#pragma unroll
        for (int nn = 0; nn < 16; nn++) {
            float4 c0 = *(float4*)&CsT[nn * 132 + ts * 8];
            float4 c1 = *(float4*)&CsT[nn * 132 + ts * 8 + 4];
            float4 b0 = *(float4*)&BsT[nn * 132 + tj * 8];
            float4 b1 = *(float4*)&BsT[nn * 132 + tj * 8 + 4];
            float cv[8] = {c0.x, c0.y, c0.z, c0.w, c1.x, c1.y, c1.z, c1.w};
            float bv[8] = {b0.x, b0.y, b0.z, b0.w, b1.x, b1.y, b1.z, b1.w};
#pragma unroll
            for (int i = 0; i < 8; i++)
#pragma unroll
                for (int k = 0; k < 8; k++) acc[i][k] += cv[i] * bv[k];
        }
        __syncthreads();
    }
#pragma unroll
    for (int i = 0; i < 8; i++) {
        size_t row = (size_t)(c * CH + ts * 8 + i) * CH;
        *(float4*)&g_Gram[row + tj * 8]     = make_float4(acc[i][0], acc[i][1], acc[i][2], acc[i][3]);
        *(float4*)&g_Gram[row + tj * 8 + 4] = make_float4(acc[i][4], acc[i][5], acc[i][6], acc[i][7]);
    }
}

// ---------------- split C block into bf16 hi/lo (for inter GEMM) --------------
__global__ void csplit_kernel()
{
    int i = blockIdx.x * 256 + threadIdx.x;   // over SEQ * 64 pairs
    if (i >= SEQ * (DSTATE / 2)) return;
    int t = i >> 6, n2 = (i & 63) * 2;
    float2 v = *(const float2*)&g_xbc[(size_t)t * DCONVIN + DINNER + DSTATE + n2];
    float h0 = bf16r(v.x), h1 = bf16r(v.y);
    g_Chi[(size_t)t * 64 + (n2 >> 1)] = packbf2(h0, h1);
    g_Clo[(size_t)t * 64 + (n2 >> 1)] = packbf2(v.x - h0, v.y - h1);
}

// ---------------- pass 1: chunk-local states S[c,h] = sum_j w_j x_j B_j^T -----
__global__ void __launch_bounds__(256) chunkstate_kernel()
{
    int bid = blockIdx.x;
    int c = bid >> 5, h = bid & 31;
    __shared__ float xs[16][68];
    __shared__ float Bs[16][132];
    __shared__ float ws[16];
    int tid = threadIdx.x;
    int tx = tid & 15, ty = tid >> 4;
    float Lend = g_L[h * SEQ + c * CH + CH - 1];
    int base = c * CH;
    float acc[4][8];
#pragma unroll
    for (int i = 0; i < 4; i++)
#pragma unroll
        for (int k = 0; k < 8; k++) acc[i][k] = 0.f;

    for (int j0 = 0; j0 < CH; j0 += 16) {
        {
            int j = tid >> 4, pq = tid & 15;
            float4 v = *(const float4*)&g_xbc[(size_t)(base + j0 + j) * DCONVIN + h * HD + pq * 4];
            *(float4*)&xs[j][pq * 4] = v;
        }
#pragma unroll
        for (int r = 0; r < 2; r++) {
            int qi = r * 256 + tid;
            int j = qi >> 5, nq = qi & 31;
            float4 v = *(const float4*)&g_xbc[(size_t)(base + j0 + j) * DCONVIN + DINNER + nq * 4];
            *(float4*)&Bs[j][nq * 4] = v;
        }
        if (tid < 16) {
            int t = base + j0 + tid;
            ws[tid] = __expf(Lend - g_L[h * SEQ + t]) * g_dt[h * SEQ + t];
        }
        __syncthreads();
#pragma unroll
        for (int jj = 0; jj < 16; jj++) {
            float w = ws[jj];
            float4 xv = *(float4*)&xs[jj][ty * 4];
            float wx[4] = {w * xv.x, w * xv.y, w * xv.z, w * xv.w};
            float4 b0 = *(float4*)&Bs[jj][tx * 8];
            float4 b1 = *(float4*)&Bs[jj][tx * 8 + 4];
            float b[8] = {b0.x, b0.y, b0.z, b0.w, b1.x, b1.y, b1.z, b1.w};
#pragma unroll
            for (int i = 0; i < 4; i++)
#pragma unroll
                for (int k = 0; k < 8; k++) acc[i][k] += wx[i] * b[k];
        }
        __syncthreads();
    }
#pragma unroll
    for (int i = 0; i < 4; i++) {
        size_t row = ((size_t)(c * NH + h) * HD + ty * 4 + i) * DSTATE;
        *(float4*)&g_S[row + tx * 8]     = make_float4(acc[i][0], acc[i][1], acc[i][2], acc[i][3]);
        *(float4*)&g_S[row + tx * 8 + 4] = make_float4(acc[i][4], acc[i][5], acc[i][6], acc[i][7]);
    }
}

// ---------------- pass 2: 32-step scan; emit H chunk-initial states as bf16 ---
__global__ void scan_kernel()
{
    int idx = blockIdx.x * 256 + threadIdx.x;   // 131072 threads, 2 n-values each
    int h = idx >> 12;
    int rem = idx & 4095;
    int p = rem >> 6;
    int n2 = (rem & 63) * 2;
    float h0 = 0.f, h1 = 0.f;
    for (int c = 0; c < NCH; c++) {
        size_t row = (size_t)c * DINNER + h * HD + p;     // Hcat row
        float b0 = bf16r(h0), b1 = bf16r(h1);
        g_Hhi[row * 64 + (n2 >> 1)] = packbf2(b0, b1);
        g_Hlo[row * 64 + (n2 >> 1)] = packbf2(h0 - b0, h1 - b1);
        float2 s = *(const float2*)&g_S[((size_t)(c * NH + h) * HD + p) * DSTATE + n2];
        float dA = expf(g_L[h * SEQ + c * CH + CH - 1]);
        h0 = dA * h0 + s.x;
        h1 = dA * h1 + s.y;
    }
}

// ---------------- pass 3: per-(chunk,head) output (intra only) ----------------
// Am[s][j] = mask * e^{Ls-Lj} dt_j * Gram[c][s][j]
// Y[s,p] = Am@X + e^{Ls} * Inter[c][s][h*64+p] + D_h x[s,p]
#define K5_SMEM_FLOATS 18240
__global__ void __launch_bounds__(256) chunkout_kernel(const float* __restrict__ Dvec)
{
    extern __shared__ float smdyn[];
    float* Am  = smdyn;            // 128*132 = 16896
    float* Xs  = smdyn + 16896;    // 16*68
    float* Ls  = smdyn + 17984;    // 128
    float* dts = smdyn + 18112;    // 128

    int bid = blockIdx.x;
    int c = bid >> 5, h = bid & 31;
    int tid = threadIdx.x;
    int ts = tid >> 4;
    int tj = tid & 15;
    int base = c * CH;

    if (tid < 128) {
        Ls[tid]  = g_L [h * SEQ + base + tid];
        dts[tid] = g_dt[h * SEQ + base + tid];
    }
    __syncthreads();

    // ---- stage 1: weight the precomputed gram matrix
    const float* Gc = g_Gram + (size_t)c * CH * CH;
#pragma unroll
    for (int i = 0; i < 8; i++) {
        int s = ts * 8 + i;
        float ls = Ls[s];
        float4 g0 = *(const float4*)&Gc[(size_t)s * CH + tj * 8];
        float4 g1 = *(const float4*)&Gc[(size_t)s * CH + tj * 8 + 4];
        float gv[8] = {g0.x, g0.y, g0.z, g0.w, g1.x, g1.y, g1.z, g1.w};
#pragma unroll
        for (int k = 0; k < 8; k++) {
            int j = tj * 8 + k;
            float w = (j <= s) ? __expf(ls - Ls[j]) * dts[j] : 0.f;
            Am[s * 132 + j] = gv[k] * w;
        }
    }
    __syncthreads();

    // ---- stage 2: Yintra = Am @ X
    float ai[8][4];
#pragma unroll
    for (int i = 0; i < 8; i++)
#pragma unroll
        for (int r = 0; r < 4; r++) ai[i][r] = 0.f;

    for (int k0 = 0; k0 < CH; k0 += 16) {
        {
            int j = tid >> 4, pq = tid & 15;
            float4 v = *(const float4*)&g_xbc[(size_t)(base + k0 + j) * DCONVIN + h * HD + pq * 4];
            *(float4*)&Xs[j * 68 + pq * 4] = v;
        }
        __syncthreads();
#pragma unroll
        for (int kk = 0; kk < 16; kk++) {
            float4 xv = *(float4*)&Xs[kk * 68 + tj * 4];
#pragma unroll
            for (int i = 0; i < 8; i++) {
                float am = Am[(ts * 8 + i) * 132 + k0 + kk];
                ai[i][0] += am * xv.x; ai[i][1] += am * xv.y;
                ai[i][2] += am * xv.z; ai[i][3] += am * xv.w;
            }
        }
        __syncthreads();
    }

    float Dh = Dvec[h];
#pragma unroll
    for (int i = 0; i < 8; i++) {
        int s = ts * 8 + i;
        int trow = base + s;
        float es = expf(Ls[s]);
        const float* Irow = g_Inter + ((size_t)(c * CH + s)) * DINNER + h * HD;
#pragma unroll
        for (int r = 0; r < 4; r++) {
            int p = tj * 4 + r;
            float xval = g_xbc[(size_t)trow * DCONVIN + h * HD + p];
            g_Y[(size_t)trow * DINNER + h * HD + p] = ai[i][r] + es * Irow[p] + Dh * xval;
        }
    }
}

// ---------------- RMSNorm + SiLU gate -> split bf16 ---------------------------
__global__ void normgate_kernel(const float* __restrict__ nw, const float* __restrict__ nb)
{
    int t = blockIdx.x;
    int tid = threadIdx.x;
    __shared__ float red[256];
    float ss = 0.f;
    for (int d = tid; d < DINNER; d += 256) {
        float v = g_Y[(size_t)t * DINNER + d];
        ss += v * v;
    }
    red[tid] = ss;
    __syncthreads();
    for (int off = 128; off > 0; off >>= 1) {
        if (tid < off) red[tid] += red[tid + off];
        __syncthreads();
    }
    float inv = rsqrtf(red[0] / (float)DINNER + 1e-6f);
    for (int d = tid * 2; d < DINNER; d += 512) {
        float v0 = g_Y[(size_t)t * DINNER + d];
        float v1 = g_Y[(size_t)t * DINNER + d + 1];
        float g0 = v0 * inv * nw[d] + nb[d];
        float g1 = v1 * inv * nw[d + 1] + nb[d + 1];
        float z0 = g_zx[(size_t)t * DPROJ + d];
        float z1 = g_zx[(size_t)t * DPROJ + d + 1];
        g0 *= z0 / (1.f + expf(-z0));
        g1 *= z1 / (1.f + expf(-z1));
        float h0 = bf16r(g0), h1 = bf16r(g1);
        size_t pi = ((size_t)t * DINNER + d) >> 1;
        g_Ghi[pi] = packbf2(h0, h1);
        g_Glo[pi] = packbf2(g0 - h0, g1 - h1);
    }
}

// ---------------- launch ------------------------------------------------------
extern "C" void kernel_launch(void* const* d_in, const int* in_sizes, int n_in,
                              void* d_out, int out_size)
{
    const float* u       = (const float*)d_in[0];
    const float* W_in    = (const float*)d_in[1];
    const float* conv_w  = (const float*)d_in[2];
    const float* conv_b  = (const float*)d_in[3];
    const float* W_out   = (const float*)d_in[4];
    const float* norm_w  = (const float*)d_in[5];
    const float* norm_b  = (const float*)d_in[6];
    const float* dt_bias = (const float*)d_in[7];
    const float* A_log   = (const float*)d_in[8];
    const float* Dv      = (const float*)d_in[9];
    float* out = (float*)d_out;

    float *zx, *Inter;
    uint32_t *u16, *Whi, *Wlo, *Vhi, *Vlo, *Ghi, *Glo, *Hhi, *Hlo, *Chi, *Clo;
    cudaGetSymbolAddress((void**)&zx,   g_zx);
    cudaGetSymbolAddress((void**)&Inter,g_Inter);
    cudaGetSymbolAddress((void**)&u16,  g_u16);
    cudaGetSymbolAddress((void**)&Whi,  g_Whi);
    cudaGetSymbolAddress((void**)&Wlo,  g_Wlo);
    cudaGetSymbolAddress((void**)&Vhi,  g_Vhi);
    cudaGetSymbolAddress((void**)&Vlo,  g_Vlo);
    cudaGetSymbolAddress((void**)&Ghi,  g_Ghi);
    cudaGetSymbolAddress((void**)&Glo,  g_Glo);
    cudaGetSymbolAddress((void**)&Hhi,  g_Hhi);
    cudaGetSymbolAddress((void**)&Hlo,  g_Hlo);
    cudaGetSymbolAddress((void**)&Chi,  g_Chi);
    cudaGetSymbolAddress((void**)&Clo,  g_Clo);

    const int SM1 = 15360 * 4;   // gemm<0,0> dyn smem bytes
    const int SM2 = 20480 * 4;   // gemm<1,*> dyn smem bytes
    cudaFuncSetAttribute(gemm_bf16s_kernel<0, 0>, cudaFuncAttributeMaxDynamicSharedMemorySize, SM1);
    cudaFuncSetAttribute(gemm_bf16s_kernel<1, 0>, cudaFuncAttributeMaxDynamicSharedMemorySize, SM2);
    cudaFuncSetAttribute(gemm_bf16s_kernel<1, 1>, cudaFuncAttributeMaxDynamicSharedMemorySize, SM2);
    cudaFuncSetAttribute(chunkout_kernel, cudaFuncAttributeMaxDynamicSharedMemorySize, K5_SMEM_FLOATS * 4);

    // 0. pre-convert operands
    {
        int np;
        np = SEQ * DMODEL / 2;
        convert_round_kernel<<<(np + 255) / 256, 256>>>(u, u16, np);
        np = DPROJ * DMODEL / 2;
        convert_split_kernel<<<(np + 255) / 256, 256>>>(W_in, Whi, Wlo, np);
        np = DMODEL * DINNER / 2;
        convert_split_kernel<<<(np + 255) / 256, 256>>>(W_out, Vhi, Vlo, np);
    }
    // 1. in_proj GEMM (pipelined bf16 TC, 2 mma)
    gemm_bf16s_kernel<0, 0><<<dim3((DPROJ + 127) / 128, SEQ / 128), 256, SM1>>>(
        u16, nullptr, Whi, Wlo, zx, SEQ, DPROJ, DMODEL);
    // 2. causal depthwise conv + silu
    conv_silu_kernel<<<dim3((DCONVIN + 255) / 256, SEQ), 256>>>(conv_w, conv_b);
    // 3. dt softplus + per-chunk cumsum
    dtscan_kernel<<<NCH * NH, CH>>>(dt_bias, A_log);
    // 3b. head-independent gram matrices
    gram_kernel<<<NCH, 256>>>();
    // 3c. split C block for inter GEMM
    csplit_kernel<<<(SEQ * (DSTATE / 2) + 255) / 256, 256>>>();
    // 4. chunk-local states
    chunkstate_kernel<<<NCH * NH, 256>>>();
    // 5. inter-chunk scan (emits split-bf16 H)
    scan_kernel<<<(NH * HD * (DSTATE / 2)) / 256, 256>>>();
    // 5b. inter term: per chunk, Inter[c] = C[c] @ Hcat[c]^T  (batched TC GEMM)
    gemm_bf16s_kernel<1, 1><<<dim3(DINNER / 128, 1, NCH), 256, SM2>>>(
        Chi, Clo, Hhi, Hlo, Inter, CH, DINNER, DSTATE);
    // 6. per-chunk output (intra + inter-combine + skip)
    chunkout_kernel<<<NCH * NH, 256, K5_SMEM_FLOATS * 4>>>(Dv);
    // 7. RMSNorm + gate -> split bf16
    normgate_kernel<<<SEQ, 256>>>(norm_w, norm_b);
    // 8. out_proj GEMM (pipelined bf16 TC, 3 mma)
    gemm_bf16s_kernel<1, 0><<<dim3(DMODEL / 128, SEQ / 128), 256, SM2>>>(
        Ghi, Glo, Vhi, Vlo, out, SEQ, DMODEL, DINNER);
}

// round 9
// speedup vs baseline: 1.5151x; 1.0202x over previous
#include <cuda_runtime.h>
#include <cuda_bf16.h>
#include <cstdint>

#define SEQ     4096
#define DMODEL  1024
#define DPROJ   4384
#define DINNER  2048
#define DCONVIN 2304
#define DSTATE  128
#define NH      32
#define HD      64
#define NCH     32
#define CH      128

// ---------------- scratch (static __device__, allocation-free) ----------------
__device__ float g_zx [SEQ * DPROJ];          // in_proj output [t][4384]
__device__ float g_xbc[SEQ * DCONVIN];        // conv+silu: x[0,2048) B[2048,2176) C[2176,2304)
__device__ float g_dt [NH * SEQ];             // softplus(dt), [h][t]
__device__ float g_L  [NH * SEQ];             // per-chunk inclusive cumsum of dt*A, [h][t]
__device__ float g_S  [NCH * NH * HD * DSTATE]; // chunk-local states
__device__ float g_Y  [SEQ * DINNER];         // ssm output
__device__ float g_Gram[NCH * CH * CH];       // per-chunk C.B^T gram (head-independent)
__device__ float g_Inter[NCH * CH * DINNER];  // per-chunk inter-term C @ Hcat^T

// pre-converted bf16 operands (packed bf16x2 in uint32)
__device__ uint32_t g_u16[SEQ * DMODEL / 2];
__device__ uint32_t g_Whi[DPROJ * DMODEL / 2];
__device__ uint32_t g_Wlo[DPROJ * DMODEL / 2];
__device__ uint32_t g_Vhi[DMODEL * DINNER / 2];
__device__ uint32_t g_Vlo[DMODEL * DINNER / 2];
__device__ uint32_t g_Ghi[SEQ * DINNER / 2];
__device__ uint32_t g_Glo[SEQ * DINNER / 2];
__device__ uint32_t g_Hhi[NCH * DINNER * DSTATE / 2];  // chunk-initial states, split bf16
__device__ uint32_t g_Hlo[NCH * DINNER * DSTATE / 2];  // rows: c*2048 + h*64+p, cols: n pairs
__device__ uint32_t g_Chi[SEQ * DSTATE / 2];           // C block split, rows t, cols n pairs
__device__ uint32_t g_Clo[SEQ * DSTATE / 2];

__device__ __forceinline__ float bf16r(float x) {
    return __bfloat162float(__float2bfloat16(x));
}
__device__ __forceinline__ uint32_t packbf2(float x, float y) {
    __nv_bfloat162 t = __floats2bfloat162_rn(x, y);
    return *(uint32_t*)&t;
}
__device__ __forceinline__ void cp16(void* sdst, const void* gsrc, int sz) {
    uint32_t sa = (uint32_t)__cvta_generic_to_shared(sdst);
    asm volatile("cp.async.cg.shared.global [%0], [%1], 16, %2;" :: "r"(sa), "l"(gsrc), "r"(sz));
}
__device__ __forceinline__ void ldsm4(uint32_t& r0, uint32_t& r1, uint32_t& r2, uint32_t& r3,
                                      uint32_t saddr) {
    asm volatile("ldmatrix.sync.aligned.m8n8.x4.shared.b16 {%0,%1,%2,%3}, [%4];"
                 : "=r"(r0), "=r"(r1), "=r"(r2), "=r"(r3) : "r"(saddr));
}

#define MMA_BF16(d, a, b)                                                        \
    asm volatile("mma.sync.aligned.m16n8k16.row.col.f32.bf16.bf16.f32 "          \
                 "{%0,%1,%2,%3}, {%4,%5,%6,%7}, {%8,%9}, {%0,%1,%2,%3};"         \
                 : "+f"(d[0]), "+f"(d[1]), "+f"(d[2]), "+f"(d[3])                \
                 : "r"(a[0]), "r"(a[1]), "r"(a[2]), "r"(a[3]),                   \
                   "r"(b[0]), "r"(b[1]))

// ---------------- operand conversion kernels ----------------------------------
__global__ void convert_round_kernel(const float* __restrict__ src, uint32_t* __restrict__ dst, int npairs)
{
    int i = blockIdx.x * 256 + threadIdx.x;
    if (i >= npairs) return;
    float2 v = *(const float2*)(src + (size_t)i * 2);
    dst[i] = packbf2(v.x, v.y);
}
__global__ void convert_split_kernel(const float* __restrict__ src,
                                     uint32_t* __restrict__ hi, uint32_t* __restrict__ lo, int npairs)
{
    int i = blockIdx.x * 256 + threadIdx.x;
    if (i >= npairs) return;
    float2 v = *(const float2*)(src + (size_t)i * 2);
    float hx = bf16r(v.x), hy = bf16r(v.y);
    hi[i] = packbf2(hx, hy);
    lo[i] = packbf2(v.x - hx, v.y - hy);
}

// ---------------- tensor-core NT GEMM, cp.async pipeline + ldmatrix frags -----
// C[M,N] = A[M,K] * B[N,K]^T, operands pre-split bf16 hi/lo planes.
//   HAS_ALO=0: 2 mma (A exact);  HAS_ALO=1: 3 mma (drop lo*lo)
//   CHUNKZ=1: batched over blockIdx.z with fixed per-chunk strides (inter GEMM)
template<int HAS_ALO, int CHUNKZ = 0>
__global__ void __launch_bounds__(256) gemm_bf16s_kernel(
    const uint32_t* __restrict__ Ahi_g, const uint32_t* __restrict__ Alo_g,
    const uint32_t* __restrict__ Bhi_g, const uint32_t* __restrict__ Blo_g,
    float* __restrict__ C, int M, int N, int K)
{
    extern __shared__ uint32_t smem[];
    // u32-unit offsets inside dyn smem
    const uint32_t ALS_O = 5120;
    const uint32_t BHS_O = 5120 + (HAS_ALO ? 5120 : 0);
    const uint32_t BLS_O = BHS_O + 5120;
    uint32_t* Ahs = smem;
    uint32_t* Als = smem + ALS_O;
    uint32_t* Bhs = smem + BHS_O;
    uint32_t* Bls = smem + BLS_O;

    if (CHUNKZ) {
        size_t cz = blockIdx.z;
        Ahi_g += cz * (size_t)CH * (DSTATE / 2);
        if (HAS_ALO) Alo_g += cz * (size_t)CH * (DSTATE / 2);
        Bhi_g += cz * (size_t)DINNER * (DSTATE / 2);
        Blo_g += cz * (size_t)DINNER * (DSTATE / 2);
        C     += cz * (size_t)CH * DINNER;
    }

    const int K2 = K >> 1;
    const int KT = K2 >> 4;
    const int bn = blockIdx.x * 128;
    const int bm = blockIdx.y * 128;
    const int tid = threadIdx.x;
    const int lane = tid & 31;
    const int wid = tid >> 5;
    const int warpM = wid >> 2;
    const int warpN = wid & 3;
    const int g = lane >> 2;
    const int tig = lane & 3;

    // ldmatrix lane-address offsets (bytes)
    const uint32_t sb32 = (uint32_t)__cvta_generic_to_shared(smem);
    const uint32_t AOFF = ((lane & 15) * 20 + (lane >> 4) * 4) * 4;
    const uint32_t BOFF = (((lane & 7) + (lane >> 4) * 8) * 20 + ((lane >> 3) & 1) * 4) * 4;

    auto issue = [&](int kt, int buf) {
        int k0 = kt * 16;
        int bo = buf * 2560;
#pragma unroll
        for (int r = 0; r < 2; r++) {
            int qi = r * 256 + tid;
            int row = qi >> 2;
            int q4 = (qi & 3) * 4;
            size_t ga = (size_t)(bm + row) * K2 + k0 + q4;
            cp16(&Ahs[bo + row * 20 + q4], Ahi_g + ga, 16);
            if (HAS_ALO) cp16(&Als[bo + row * 20 + q4], Alo_g + ga, 16);
            int nn = bn + row;
            int sz = (nn < N) ? 16 : 0;
            size_t gb = (size_t)((nn < N) ? nn : 0) * K2 + k0 + q4;
            cp16(&Bhs[bo + row * 20 + q4], Bhi_g + gb, sz);
            cp16(&Bls[bo + row * 20 + q4], Blo_g + gb, sz);
        }
        asm volatile("cp.async.commit_group;" ::: "memory");
    };

    float acc[4][4][4];
#pragma unroll
    for (int mt = 0; mt < 4; mt++)
#pragma unroll
        for (int nt = 0; nt < 4; nt++)
#pragma unroll
            for (int e = 0; e < 4; e++) acc[mt][nt][e] = 0.f;

    issue(0, 0);

    for (int kt = 0; kt < KT; kt++) {
        int buf = kt & 1;
        if (kt + 1 < KT) {
            issue(kt + 1, buf ^ 1);
            asm volatile("cp.async.wait_group 1;" ::: "memory");
        } else {
            asm volatile("cp.async.wait_group 0;" ::: "memory");
        }
        __syncthreads();

        const uint32_t bo4 = (uint32_t)(buf * 2560) * 4;
#pragma unroll
        for (int kh = 0; kh < 2; kh++) {
            const uint32_t kb4 = (uint32_t)(kh * 8) * 4;
            uint32_t bhi[4][2], blo[4][2];
#pragma unroll
            for (int ntp = 0; ntp < 2; ntp++) {
                uint32_t nbase = sb32 + bo4 + (uint32_t)((warpN * 32 + ntp * 16) * 20) * 4 + kb4 + BOFF;
                ldsm4(bhi[ntp * 2][0], bhi[ntp * 2][1], bhi[ntp * 2 + 1][0], bhi[ntp * 2 + 1][1],
                      nbase + BHS_O * 4);
                ldsm4(blo[ntp * 2][0], blo[ntp * 2][1], blo[ntp * 2 + 1][0], blo[ntp * 2 + 1][1],
                      nbase + BLS_O * 4);
            }
#pragma unroll
            for (int mt = 0; mt < 4; mt++) {
                uint32_t abase = sb32 + bo4 + (uint32_t)((warpM * 64 + mt * 16) * 20) * 4 + kb4 + AOFF;
                uint32_t ah[4], al[4];
                ldsm4(ah[0], ah[1], ah[2], ah[3], abase);
                if (HAS_ALO) ldsm4(al[0], al[1], al[2], al[3], abase + ALS_O * 4);
#pragma unroll
                for (int nt = 0; nt < 4; nt++) MMA_BF16(acc[mt][nt], ah, bhi[nt]);
#pragma unroll
                for (int nt = 0; nt < 4; nt++) MMA_BF16(acc[mt][nt], ah, blo[nt]);
                if (HAS_ALO) {
#pragma unroll
                    for (int nt = 0; nt < 4; nt++) MMA_BF16(acc[mt][nt], al, bhi[nt]);
                }
            }
        }
        __syncthreads();
    }

#pragma unroll
    for (int mt = 0; mt < 4; mt++) {
        int row = bm + warpM * 64 + mt * 16 + g;
#pragma unroll
        for (int nt = 0; nt < 4; nt++) {
            int col = bn + warpN * 32 + nt * 8 + tig * 2;
            if (col < N) {
                C[(size_t)row * N + col]           = acc[mt][nt][0];
                C[(size_t)row * N + col + 1]       = acc[mt][nt][1];
                C[(size_t)(row + 8) * N + col]     = acc[mt][nt][2];
                C[(size_t)(row + 8) * N + col + 1] = acc[mt][nt][3];
            }
        }
    }
}

// ---------------- causal depthwise conv(4) + SiLU (8 timesteps/thread) --------
__global__ void conv_silu_kernel(const float* __restrict__ cw, const float* __restrict__ cb)
{
    int c = blockIdx.x * 256 + threadIdx.x;
    if (c >= DCONVIN) return;
    int t0 = blockIdx.y * 8;
    float w0 = cw[c * 4], w1 = cw[c * 4 + 1], w2 = cw[c * 4 + 2], w3 = cw[c * 4 + 3];
    float bias = cb[c];
    float v[11];
#pragma unroll
    for (int i = 0; i < 11; i++) {
        int tt = t0 - 3 + i;
        v[i] = (tt >= 0) ? g_zx[(size_t)tt * DPROJ + DINNER + c] : 0.f;
    }
#pragma unroll
    for (int i = 0; i < 8; i++) {
        float s = bias + v[i] * w0 + v[i + 1] * w1 + v[i + 2] * w2 + v[i + 3] * w3;
        g_xbc[(size_t)(t0 + i) * DCONVIN + c] = s / (1.f + expf(-s));
    }
}

// ---------------- softplus(dt)+dt_bias, dt*A, per-chunk inclusive cumsum ------
__global__ void dtscan_kernel(const float* __restrict__ dt_bias, const float* __restrict__ A_log)
{
    int bid = blockIdx.x;
    int c = bid >> 5, h = bid & 31;
    int s = threadIdx.x;
    int t = c * CH + s;
    float raw = g_zx[(size_t)t * DPROJ + (DINNER + DINNER + 2 * DSTATE) + h] + dt_bias[h];
    float dtv = (raw > 20.f) ? raw : log1pf(expf(raw));
    float Ah = -expf(A_log[h]);
    __shared__ float sm[CH];
    sm[s] = dtv * Ah;
    g_dt[h * SEQ + t] = dtv;
    __syncthreads();
    for (int off = 1; off < CH; off <<= 1) {
        float add = (s >= off) ? sm[s - off] : 0.f;
        __syncthreads();
        sm[s] += add;
        __syncthreads();
    }
    g_L[h * SEQ + t] = sm[s];
}

// ---------------- gram: G[c][s][j] = C_s . B_j (head-independent, NGROUPS=1) --
__global__ void __launch_bounds__(256) gram_kernel()
{
    int c = blockIdx.x;
    __shared__ float CsT[16 * 132];
    __shared__ float BsT[16 * 132];
    int tid = threadIdx.x;
    int ts = tid >> 4, tj = tid & 15;
    int base = c * CH;

    float acc[8][8];
#pragma unroll
    for (int i = 0; i < 8; i++)
#pragma unroll
        for (int k = 0; k < 8; k++) acc[i][k] = 0.f;

    for (int n0 = 0; n0 < DSTATE; n0 += 16) {
#pragma unroll
        for (int r = 0; r < 2; r++) {
            int qi = r * 256 + tid;
            int s = qi >> 2, nq = qi & 3;
            float4 vc = *(const float4*)&g_xbc[(size_t)(base + s) * DCONVIN + DINNER + DSTATE + n0 + nq * 4];
            CsT[(nq * 4 + 0) * 132 + s] = vc.x; CsT[(nq * 4 + 1) * 132 + s] = vc.y;
            CsT[(nq * 4 + 2) * 132 + s] = vc.z; CsT[(nq * 4 + 3) * 132 + s] = vc.w;
            float4 vb = *(const float4*)&g_xbc[(size_t)(base + s) * DCONVIN + DINNER + n0 + nq * 4];
            BsT[(nq * 4 + 0) * 132 + s] = vb.x; BsT[(nq * 4 + 1) * 132 + s] = vb.y;
            BsT[(nq * 4 + 2) * 132 + s] = vb.z; BsT[(nq * 4 + 3) * 132 + s] = vb.w;
        }
        __syncthreads();
#pragma unroll
        for (int nn = 0; nn < 16; nn++) {
            float4 c0 = *(float4*)&CsT[nn * 132 + ts * 8];
            float4 c1 = *(float4*)&CsT[nn * 132 + ts * 8 + 4];
            float4 b0 = *(float4*)&BsT[nn * 132 + tj * 8];
            float4 b1 = *(float4*)&BsT[nn * 132 + tj * 8 + 4];
            float cv[8] = {c0.x, c0.y, c0.z, c0.w, c1.x, c1.y, c1.z, c1.w};
            float bv[8] = {b0.x, b0.y, b0.z, b0.w, b1.x, b1.y, b1.z, b1.w};
#pragma unroll
            for (int i = 0; i < 8; i++)
#pragma unroll
                for (int k = 0; k < 8; k++) acc[i][k] += cv[i] * bv[k];
        }
        __syncthreads();
    }
#pragma unroll
    for (int i = 0; i < 8; i++) {
        size_t row = (size_t)(c * CH + ts * 8 + i) * CH;
        *(float4*)&g_Gram[row + tj * 8]     = make_float4(acc[i][0], acc[i][1], acc[i][2], acc[i][3]);
        *(float4*)&g_Gram[row + tj * 8 + 4] = make_float4(acc[i][4], acc[i][5], acc[i][6], acc[i][7]);
    }
}

// ---------------- split C block into bf16 hi/lo (for inter GEMM) --------------
__global__ void csplit_kernel()
{
    int i = blockIdx.x * 256 + threadIdx.x;   // over SEQ * 64 pairs
    if (i >= SEQ * (DSTATE / 2)) return;
    int t = i >> 6, n2 = (i & 63) * 2;
    float2 v = *(const float2*)&g_xbc[(size_t)t * DCONVIN + DINNER + DSTATE + n2];
    float h0 = bf16r(v.x), h1 = bf16r(v.y);
    g_Chi[(size_t)t * 64 + (n2 >> 1)] = packbf2(h0, h1);
    g_Clo[(size_t)t * 64 + (n2 >> 1)] = packbf2(v.x - h0, v.y - h1);
}

// ---------------- pass 1: chunk-local states S[c,h] = sum_j w_j x_j B_j^T -----
__global__ void __launch_bounds__(256) chunkstate_kernel()
{
    int bid = blockIdx.x;
    int c = bid >> 5, h = bid & 31;
    __shared__ float xs[16][68];
    __shared__ float Bs[16][132];
    __shared__ float ws[16];
    int tid = threadIdx.x;
    int tx = tid & 15, ty = tid >> 4;
    float Lend = g_L[h * SEQ + c * CH + CH - 1];
    int base = c * CH;
    float acc[4][8];
#pragma unroll
    for (int i = 0; i < 4; i++)
#pragma unroll
        for (int k = 0; k < 8; k++) acc[i][k] = 0.f;

    for (int j0 = 0; j0 < CH; j0 += 16) {
        {
            int j = tid >> 4, pq = tid & 15;
            float4 v = *(const float4*)&g_xbc[(size_t)(base + j0 + j) * DCONVIN + h * HD + pq * 4];
            *(float4*)&xs[j][pq * 4] = v;
        }
#pragma unroll
        for (int r = 0; r < 2; r++) {
            int qi = r * 256 + tid;
            int j = qi >> 5, nq = qi & 31;
            float4 v = *(const float4*)&g_xbc[(size_t)(base + j0 + j) * DCONVIN + DINNER + nq * 4];
            *(float4*)&Bs[j][nq * 4] = v;
        }
        if (tid < 16) {
            int t = base + j0 + tid;
            ws[tid] = __expf(Lend - g_L[h * SEQ + t]) * g_dt[h * SEQ + t];
        }
        __syncthreads();
#pragma unroll
        for (int jj = 0; jj < 16; jj++) {
            float w = ws[jj];
            float4 xv = *(float4*)&xs[jj][ty * 4];
            float wx[4] = {w * xv.x, w * xv.y, w * xv.z, w * xv.w};
            float4 b0 = *(float4*)&Bs[jj][tx * 8];
            float4 b1 = *(float4*)&Bs[jj][tx * 8 + 4];
            float b[8] = {b0.x, b0.y, b0.z, b0.w, b1.x, b1.y, b1.z, b1.w};
#pragma unroll
            for (int i = 0; i < 4; i++)
#pragma unroll
                for (int k = 0; k < 8; k++) acc[i][k] += wx[i] * b[k];
        }
        __syncthreads();
    }
#pragma unroll
    for (int i = 0; i < 4; i++) {
        size_t row = ((size_t)(c * NH + h) * HD + ty * 4 + i) * DSTATE;
        *(float4*)&g_S[row + tx * 8]     = make_float4(acc[i][0], acc[i][1], acc[i][2], acc[i][3]);
        *(float4*)&g_S[row + tx * 8 + 4] = make_float4(acc[i][4], acc[i][5], acc[i][6], acc[i][7]);
    }
}

// ---------------- pass 2: 32-step scan; emit H chunk-initial states as bf16 ---
__global__ void scan_kernel()
{
    int idx = blockIdx.x * 256 + threadIdx.x;   // 131072 threads, 2 n-values each
    int h = idx >> 12;
    int rem = idx & 4095;
    int p = rem >> 6;
    int n2 = (rem & 63) * 2;
    float h0 = 0.f, h1 = 0.f;
    for (int c = 0; c < NCH; c++) {
        size_t row = (size_t)c * DINNER + h * HD + p;     // Hcat row
        float b0 = bf16r(h0), b1 = bf16r(h1);
        g_Hhi[row * 64 + (n2 >> 1)] = packbf2(b0, b1);
        g_Hlo[row * 64 + (n2 >> 1)] = packbf2(h0 - b0, h1 - b1);
        float2 s = *(const float2*)&g_S[((size_t)(c * NH + h) * HD + p) * DSTATE + n2];
        float dA = expf(g_L[h * SEQ + c * CH + CH - 1]);
        h0 = dA * h0 + s.x;
        h1 = dA * h1 + s.y;
    }
}

// ---------------- pass 3: per-(chunk,head) output (intra only) ----------------
// Am[s][j] = mask * e^{Ls-Lj} dt_j * Gram[c][s][j]
// Y[s,p] = Am@X + e^{Ls} * Inter[c][s][h*64+p] + D_h x[s,p]
#define K5_SMEM_FLOATS 18240
__global__ void __launch_bounds__(256) chunkout_kernel(const float* __restrict__ Dvec)
{
    extern __shared__ float smdyn[];
    float* Am  = smdyn;            // 128*132 = 16896
    float* Xs  = smdyn + 16896;    // 16*68
    float* Ls  = smdyn + 17984;    // 128
    float* dts = smdyn + 18112;    // 128

    int bid = blockIdx.x;
    int c = bid >> 5, h = bid & 31;
    int tid = threadIdx.x;
    int ts = tid >> 4;
    int tj = tid & 15;
    int base = c * CH;

    if (tid < 128) {
        Ls[tid]  = g_L [h * SEQ + base + tid];
        dts[tid] = g_dt[h * SEQ + base + tid];
    }
    __syncthreads();

    // ---- stage 1: weight the precomputed gram matrix
    const float* Gc = g_Gram + (size_t)c * CH * CH;
#pragma unroll
    for (int i = 0; i < 8; i++) {
        int s = ts * 8 + i;
        float ls = Ls[s];
        float4 g0 = *(const float4*)&Gc[(size_t)s * CH + tj * 8];
        float4 g1 = *(const float4*)&Gc[(size_t)s * CH + tj * 8 + 4];
        float gv[8] = {g0.x, g0.y, g0.z, g0.w, g1.x, g1.y, g1.z, g1.w};
#pragma unroll
        for (int k = 0; k < 8; k++) {
            int j = tj * 8 + k;
            float w = (j <= s) ? __expf(ls - Ls[j]) * dts[j] : 0.f;
            Am[s * 132 + j] = gv[k] * w;
        }
    }
    __syncthreads();

    // ---- stage 2: Yintra = Am @ X
    float ai[8][4];
#pragma unroll
    for (int i = 0; i < 8; i++)
#pragma unroll
        for (int r = 0; r < 4; r++) ai[i][r] = 0.f;

    for (int k0 = 0; k0 < CH; k0 += 16) {
        {
            int j = tid >> 4, pq = tid & 15;
            float4 v = *(const float4*)&g_xbc[(size_t)(base + k0 + j) * DCONVIN + h * HD + pq * 4];
            *(float4*)&Xs[j * 68 + pq * 4] = v;
        }
        __syncthreads();
#pragma unroll
        for (int kk = 0; kk < 16; kk++) {
            float4 xv = *(float4*)&Xs[kk * 68 + tj * 4];
#pragma unroll
            for (int i = 0; i < 8; i++) {
                float am = Am[(ts * 8 + i) * 132 + k0 + kk];
                ai[i][0] += am * xv.x; ai[i][1] += am * xv.y;
                ai[i][2] += am * xv.z; ai[i][3] += am * xv.w;
            }
        }
        __syncthreads();
    }

    float Dh = Dvec[h];
#pragma unroll
    for (int i = 0; i < 8; i++) {
        int s = ts * 8 + i;
        int trow = base + s;
        float es = expf(Ls[s]);
        const float* Irow = g_Inter + ((size_t)(c * CH + s)) * DINNER + h * HD;
#pragma unroll
        for (int r = 0; r < 4; r++) {
            int p = tj * 4 + r;
            float xval = g_xbc[(size_t)trow * DCONVIN + h * HD + p];
            g_Y[(size_t)trow * DINNER + h * HD + p] = ai[i][r] + es * Irow[p] + Dh * xval;
        }
    }
}

// ---------------- RMSNorm + SiLU gate -> split bf16 ---------------------------
__global__ void normgate_kernel(const float* __restrict__ nw, const float* __restrict__ nb)
{
    int t = blockIdx.x;
    int tid = threadIdx.x;
    __shared__ float red[256];
    float ss = 0.f;
    for (int d = tid; d < DINNER; d += 256) {
        float v = g_Y[(size_t)t * DINNER + d];
        ss += v * v;
    }
    red[tid] = ss;
    __syncthreads();
    for (int off = 128; off > 0; off >>= 1) {
        if (tid < off) red[tid] += red[tid + off];
        __syncthreads();
    }
    float inv = rsqrtf(red[0] / (float)DINNER + 1e-6f);
    for (int d = tid * 2; d < DINNER; d += 512) {
        float v0 = g_Y[(size_t)t * DINNER + d];
        float v1 = g_Y[(size_t)t * DINNER + d + 1];
        float g0 = v0 * inv * nw[d] + nb[d];
        float g1 = v1 * inv * nw[d + 1] + nb[d + 1];
        float z0 = g_zx[(size_t)t * DPROJ + d];
        float z1 = g_zx[(size_t)t * DPROJ + d + 1];
        g0 *= z0 / (1.f + expf(-z0));
        g1 *= z1 / (1.f + expf(-z1));
        float h0 = bf16r(g0), h1 = bf16r(g1);
        size_t pi = ((size_t)t * DINNER + d) >> 1;
        g_Ghi[pi] = packbf2(h0, h1);
        g_Glo[pi] = packbf2(g0 - h0, g1 - h1);
    }
}

// ---------------- launch ------------------------------------------------------
extern "C" void kernel_launch(void* const* d_in, const int* in_sizes, int n_in,
                              void* d_out, int out_size)
{
    const float* u       = (const float*)d_in[0];
    const float* W_in    = (const float*)d_in[1];
    const float* conv_w  = (const float*)d_in[2];
    const float* conv_b  = (const float*)d_in[3];
    const float* W_out   = (const float*)d_in[4];
    const float* norm_w  = (const float*)d_in[5];
    const float* norm_b  = (const float*)d_in[6];
    const float* dt_bias = (const float*)d_in[7];
    const float* A_log   = (const float*)d_in[8];
    const float* Dv      = (const float*)d_in[9];
    float* out = (float*)d_out;

    float *zx, *Inter;
    uint32_t *u16, *Whi, *Wlo, *Vhi, *Vlo, *Ghi, *Glo, *Hhi, *Hlo, *Chi, *Clo;
    cudaGetSymbolAddress((void**)&zx,   g_zx);
    cudaGetSymbolAddress((void**)&Inter,g_Inter);
    cudaGetSymbolAddress((void**)&u16,  g_u16);
    cudaGetSymbolAddress((void**)&Whi,  g_Whi);
    cudaGetSymbolAddress((void**)&Wlo,  g_Wlo);
    cudaGetSymbolAddress((void**)&Vhi,  g_Vhi);
    cudaGetSymbolAddress((void**)&Vlo,  g_Vlo);
    cudaGetSymbolAddress((void**)&Ghi,  g_Ghi);
    cudaGetSymbolAddress((void**)&Glo,  g_Glo);
    cudaGetSymbolAddress((void**)&Hhi,  g_Hhi);
    cudaGetSymbolAddress((void**)&Hlo,  g_Hlo);
    cudaGetSymbolAddress((void**)&Chi,  g_Chi);
    cudaGetSymbolAddress((void**)&Clo,  g_Clo);

    const int SM1 = 15360 * 4;   // gemm<0,0> dyn smem bytes
    const int SM2 = 20480 * 4;   // gemm<1,*> dyn smem bytes
    cudaFuncSetAttribute(gemm_bf16s_kernel<0, 0>, cudaFuncAttributeMaxDynamicSharedMemorySize, SM1);
    cudaFuncSetAttribute(gemm_bf16s_kernel<1, 0>, cudaFuncAttributeMaxDynamicSharedMemorySize, SM2);
    cudaFuncSetAttribute(gemm_bf16s_kernel<1, 1>, cudaFuncAttributeMaxDynamicSharedMemorySize, SM2);
    cudaFuncSetAttribute(chunkout_kernel, cudaFuncAttributeMaxDynamicSharedMemorySize, K5_SMEM_FLOATS * 4);

    // 0. pre-convert operands
    {
        int np;
        np = SEQ * DMODEL / 2;
        convert_round_kernel<<<(np + 255) / 256, 256>>>(u, u16, np);
        np = DPROJ * DMODEL / 2;
        convert_split_kernel<<<(np + 255) / 256, 256>>>(W_in, Whi, Wlo, np);
        np = DMODEL * DINNER / 2;
        convert_split_kernel<<<(np + 255) / 256, 256>>>(W_out, Vhi, Vlo, np);
    }
    // 1. in_proj GEMM (pipelined bf16 TC + ldmatrix, 2 mma)
    gemm_bf16s_kernel<0, 0><<<dim3((DPROJ + 127) / 128, SEQ / 128), 256, SM1>>>(
        u16, nullptr, Whi, Wlo, zx, SEQ, DPROJ, DMODEL);
    // 2. causal depthwise conv + silu (8 t/thread)
    conv_silu_kernel<<<dim3((DCONVIN + 255) / 256, SEQ / 8), 256>>>(conv_w, conv_b);
    // 3. dt softplus + per-chunk cumsum
    dtscan_kernel<<<NCH * NH, CH>>>(dt_bias, A_log);
    // 3b. head-independent gram matrices
    gram_kernel<<<NCH, 256>>>();
    // 3c. split C block for inter GEMM
    csplit_kernel<<<(SEQ * (DSTATE / 2) + 255) / 256, 256>>>();
    // 4. chunk-local states
    chunkstate_kernel<<<NCH * NH, 256>>>();
    // 5. inter-chunk scan (emits split-bf16 H)
    scan_kernel<<<(NH * HD * (DSTATE / 2)) / 256, 256>>>();
    // 5b. inter term: per chunk, Inter[c] = C[c] @ Hcat[c]^T  (batched TC GEMM)
    gemm_bf16s_kernel<1, 1><<<dim3(DINNER / 128, 1, NCH), 256, SM2>>>(
        Chi, Clo, Hhi, Hlo, Inter, CH, DINNER, DSTATE);
    // 6. per-chunk output (intra + inter-combine + skip)
    chunkout_kernel<<<NCH * NH, 256, K5_SMEM_FLOATS * 4>>>(Dv);
    // 7. RMSNorm + gate -> split bf16
    normgate_kernel<<<SEQ, 256>>>(norm_w, norm_b);
    // 8. out_proj GEMM (pipelined bf16 TC + ldmatrix, 3 mma)
    gemm_bf16s_kernel<1, 0><<<dim3(DMODEL / 128, SEQ / 128), 256, SM2>>>(
        Ghi, Glo, Vhi, Vlo, out, SEQ, DMODEL, DINNER);
}

// round 10
// speedup vs baseline: 1.6694x; 1.1019x over previous
#include <cuda_runtime.h>
#include <cuda_bf16.h>
#include <cstdint>

#define SEQ     4096
#define DMODEL  1024
#define DPROJ   4384
#define DINNER  2048
#define DCONVIN 2304
#define DSTATE  128
#define NH      32
#define HD      64
#define NCH     32
#define CH      128

// ---------------- scratch (static __device__, allocation-free) ----------------
__device__ float g_zx [SEQ * DPROJ];          // in_proj output [t][4384]
__device__ float g_xbc[SEQ * DCONVIN];        // conv+silu: x[0,2048) B[2048,2176) C[2176,2304)
__device__ float g_dt [NH * SEQ];             // softplus(dt), [h][t]
__device__ float g_L  [NH * SEQ];             // per-chunk inclusive cumsum of dt*A, [h][t]
__device__ float g_S  [NCH * NH * HD * DSTATE]; // chunk-local states
__device__ float g_Y  [SEQ * DINNER];         // ssm output
__device__ float g_Gram[NCH * CH * CH];       // per-chunk C.B^T gram (head-independent)
__device__ float g_Inter[NCH * CH * DINNER];  // per-chunk inter-term C @ Hcat^T

// pre-converted bf16 operands (packed bf16x2 in uint32)
__device__ uint32_t g_u16[SEQ * DMODEL / 2];
__device__ uint32_t g_Whi[DPROJ * DMODEL / 2];
__device__ uint32_t g_Wlo[DPROJ * DMODEL / 2];
__device__ uint32_t g_Vhi[DMODEL * DINNER / 2];
__device__ uint32_t g_Vlo[DMODEL * DINNER / 2];
__device__ uint32_t g_Ghi[SEQ * DINNER / 2];
__device__ uint32_t g_Glo[SEQ * DINNER / 2];
__device__ uint32_t g_Hhi[NCH * DINNER * DSTATE / 2];  // chunk-initial states, split bf16
__device__ uint32_t g_Hlo[NCH * DINNER * DSTATE / 2];
__device__ uint32_t g_Chi[SEQ * DSTATE / 2];           // C block split
__device__ uint32_t g_Clo[SEQ * DSTATE / 2];

__device__ __forceinline__ float bf16r(float x) {
    return __bfloat162float(__float2bfloat16(x));
}
__device__ __forceinline__ uint32_t packbf2(float x, float y) {
    __nv_bfloat162 t = __floats2bfloat162_rn(x, y);
    return *(uint32_t*)&t;
}
__device__ __forceinline__ void cp16(void* sdst, const void* gsrc, int sz) {
    uint32_t sa = (uint32_t)__cvta_generic_to_shared(sdst);
    asm volatile("cp.async.cg.shared.global [%0], [%1], 16, %2;" :: "r"(sa), "l"(gsrc), "r"(sz));
}
__device__ __forceinline__ void ldsm4(uint32_t& r0, uint32_t& r1, uint32_t& r2, uint32_t& r3,
                                      uint32_t saddr) {
    asm volatile("ldmatrix.sync.aligned.m8n8.x4.shared.b16 {%0,%1,%2,%3}, [%4];"
                 : "=r"(r0), "=r"(r1), "=r"(r2), "=r"(r3) : "r"(saddr));
}
__device__ __forceinline__ void ldsm4t(uint32_t& r0, uint32_t& r1, uint32_t& r2, uint32_t& r3,
                                       uint32_t saddr) {
    asm volatile("ldmatrix.sync.aligned.m8n8.x4.trans.shared.b16 {%0,%1,%2,%3}, [%4];"
                 : "=r"(r0), "=r"(r1), "=r"(r2), "=r"(r3) : "r"(saddr));
}

#define MMA_BF16(d, a, b)                                                        \
    asm volatile("mma.sync.aligned.m16n8k16.row.col.f32.bf16.bf16.f32 "          \
                 "{%0,%1,%2,%3}, {%4,%5,%6,%7}, {%8,%9}, {%0,%1,%2,%3};"         \
                 : "+f"(d[0]), "+f"(d[1]), "+f"(d[2]), "+f"(d[3])                \
                 : "r"(a[0]), "r"(a[1]), "r"(a[2]), "r"(a[3]),                   \
                   "r"(b[0]), "r"(b[1]))

// ---------------- operand conversion kernels ----------------------------------
__global__ void convert_round_kernel(const float* __restrict__ src, uint32_t* __restrict__ dst, int npairs)
{
    int i = blockIdx.x * 256 + threadIdx.x;
    if (i >= npairs) return;
    float2 v = *(const float2*)(src + (size_t)i * 2);
    dst[i] = packbf2(v.x, v.y);
}
__global__ void convert_split_kernel(const float* __restrict__ src,
                                     uint32_t* __restrict__ hi, uint32_t* __restrict__ lo, int npairs)
{
    int i = blockIdx.x * 256 + threadIdx.x;
    if (i >= npairs) return;
    float2 v = *(const float2*)(src + (size_t)i * 2);
    float hx = bf16r(v.x), hy = bf16r(v.y);
    hi[i] = packbf2(hx, hy);
    lo[i] = packbf2(v.x - hx, v.y - hy);
}

// ---------------- tensor-core NT GEMM, cp.async pipeline + ldmatrix frags -----
// C[M,N] = A[M,K] * B[N,K]^T, operands pre-split bf16 hi/lo planes.
//   HAS_ALO=0: 2 mma (A exact);  HAS_ALO=1: 3 mma (drop lo*lo)
//   CHUNKZ=1: batched over blockIdx.z with fixed per-chunk strides (inter GEMM)
//   STAGES=3: single-sync pipeline;  STAGES=2: classic double-sync
template<int HAS_ALO, int CHUNKZ, int STAGES>
__global__ void __launch_bounds__(256) gemm_bf16s_kernel(
    const uint32_t* __restrict__ Ahi_g, const uint32_t* __restrict__ Alo_g,
    const uint32_t* __restrict__ Bhi_g, const uint32_t* __restrict__ Blo_g,
    float* __restrict__ C, int M, int N, int K)
{
    extern __shared__ uint32_t smem[];
    const uint32_t PS    = STAGES * 2560;                 // plane size (u32)
    const uint32_t ALS_O = PS;
    const uint32_t BHS_O = PS * (1 + (HAS_ALO ? 1 : 0));
    const uint32_t BLS_O = BHS_O + PS;
    uint32_t* Ahs = smem;
    uint32_t* Als = smem + ALS_O;
    uint32_t* Bhs = smem + BHS_O;
    uint32_t* Bls = smem + BLS_O;

    if (CHUNKZ) {
        size_t cz = blockIdx.z;
        Ahi_g += cz * (size_t)CH * (DSTATE / 2);
        if (HAS_ALO) Alo_g += cz * (size_t)CH * (DSTATE / 2);
        Bhi_g += cz * (size_t)DINNER * (DSTATE / 2);
        Blo_g += cz * (size_t)DINNER * (DSTATE / 2);
        C     += cz * (size_t)CH * DINNER;
    }

    const int K2 = K >> 1;
    const int KT = K2 >> 4;
    const int bn = blockIdx.x * 128;
    const int bm = blockIdx.y * 128;
    const int tid = threadIdx.x;
    const int lane = tid & 31;
    const int wid = tid >> 5;
    const int warpM = wid >> 2;
    const int warpN = wid & 3;
    const int g = lane >> 2;
    const int tig = lane & 3;

    const uint32_t sb32 = (uint32_t)__cvta_generic_to_shared(smem);
    const uint32_t AOFF = ((lane & 15) * 20 + (lane >> 4) * 4) * 4;
    const uint32_t BOFF = (((lane & 7) + (lane >> 4) * 8) * 20 + ((lane >> 3) & 1) * 4) * 4;

    auto issue = [&](int kt) {
        int k0 = kt * 16;
        int bo = (kt % STAGES) * 2560;
#pragma unroll
        for (int r = 0; r < 2; r++) {
            int qi = r * 256 + tid;
            int row = qi >> 2;
            int q4 = (qi & 3) * 4;
            size_t ga = (size_t)(bm + row) * K2 + k0 + q4;
            cp16(&Ahs[bo + row * 20 + q4], Ahi_g + ga, 16);
            if (HAS_ALO) cp16(&Als[bo + row * 20 + q4], Alo_g + ga, 16);
            int nn = bn + row;
            int sz = (nn < N) ? 16 : 0;
            size_t gb = (size_t)((nn < N) ? nn : 0) * K2 + k0 + q4;
            cp16(&Bhs[bo + row * 20 + q4], Bhi_g + gb, sz);
            cp16(&Bls[bo + row * 20 + q4], Blo_g + gb, sz);
        }
        asm volatile("cp.async.commit_group;" ::: "memory");
    };

    float acc[4][4][4];
#pragma unroll
    for (int mt = 0; mt < 4; mt++)
#pragma unroll
        for (int nt = 0; nt < 4; nt++)
#pragma unroll
            for (int e = 0; e < 4; e++) acc[mt][nt][e] = 0.f;

    auto compute = [&](int kt) {
        const uint32_t bo4 = (uint32_t)((kt % STAGES) * 2560) * 4;
#pragma unroll
        for (int kh = 0; kh < 2; kh++) {
            const uint32_t kb4 = (uint32_t)(kh * 8) * 4;
            uint32_t bhi[4][2], blo[4][2];
#pragma unroll
            for (int ntp = 0; ntp < 2; ntp++) {
                uint32_t nbase = sb32 + bo4 + (uint32_t)((warpN * 32 + ntp * 16) * 20) * 4 + kb4 + BOFF;
                ldsm4(bhi[ntp * 2][0], bhi[ntp * 2][1], bhi[ntp * 2 + 1][0], bhi[ntp * 2 + 1][1],
                      nbase + BHS_O * 4);
                ldsm4(blo[ntp * 2][0], blo[ntp * 2][1], blo[ntp * 2 + 1][0], blo[ntp * 2 + 1][1],
                      nbase + BLS_O * 4);
            }
#pragma unroll
            for (int mt = 0; mt < 4; mt++) {
                uint32_t abase = sb32 + bo4 + (uint32_t)((warpM * 64 + mt * 16) * 20) * 4 + kb4 + AOFF;
                uint32_t ah[4], al[4];
                ldsm4(ah[0], ah[1], ah[2], ah[3], abase);
                if (HAS_ALO) ldsm4(al[0], al[1], al[2], al[3], abase + ALS_O * 4);
#pragma unroll
                for (int nt = 0; nt < 4; nt++) MMA_BF16(acc[mt][nt], ah, bhi[nt]);
#pragma unroll
                for (int nt = 0; nt < 4; nt++) MMA_BF16(acc[mt][nt], ah, blo[nt]);
                if (HAS_ALO) {
#pragma unroll
                    for (int nt = 0; nt < 4; nt++) MMA_BF16(acc[mt][nt], al, bhi[nt]);
                }
            }
        }
    };

    if (STAGES == 3) {
        issue(0);
        issue(1);
        for (int kt = 0; kt < KT; kt++) {
            if (kt + 1 < KT) {
                asm volatile("cp.async.wait_group 1;" ::: "memory");
            } else {
                asm volatile("cp.async.wait_group 0;" ::: "memory");
            }
            __syncthreads();
            compute(kt);
            if (kt + 2 < KT) issue(kt + 2);
        }
    } else {
        issue(0);
        for (int kt = 0; kt < KT; kt++) {
            if (kt + 1 < KT) {
                issue(kt + 1);
                asm volatile("cp.async.wait_group 1;" ::: "memory");
            } else {
                asm volatile("cp.async.wait_group 0;" ::: "memory");
            }
            __syncthreads();
            compute(kt);
            __syncthreads();
        }
    }

#pragma unroll
    for (int mt = 0; mt < 4; mt++) {
        int row = bm + warpM * 64 + mt * 16 + g;
#pragma unroll
        for (int nt = 0; nt < 4; nt++) {
            int col = bn + warpN * 32 + nt * 8 + tig * 2;
            if (col < N) {
                C[(size_t)row * N + col]           = acc[mt][nt][0];
                C[(size_t)row * N + col + 1]       = acc[mt][nt][1];
                C[(size_t)(row + 8) * N + col]     = acc[mt][nt][2];
                C[(size_t)(row + 8) * N + col + 1] = acc[mt][nt][3];
            }
        }
    }
}

// ---------------- causal depthwise conv(4) + SiLU (8 timesteps/thread) --------
__global__ void conv_silu_kernel(const float* __restrict__ cw, const float* __restrict__ cb)
{
    int c = blockIdx.x * 256 + threadIdx.x;
    if (c >= DCONVIN) return;
    int t0 = blockIdx.y * 8;
    float w0 = cw[c * 4], w1 = cw[c * 4 + 1], w2 = cw[c * 4 + 2], w3 = cw[c * 4 + 3];
    float bias = cb[c];
    float v[11];
#pragma unroll
    for (int i = 0; i < 11; i++) {
        int tt = t0 - 3 + i;
        v[i] = (tt >= 0) ? g_zx[(size_t)tt * DPROJ + DINNER + c] : 0.f;
    }
#pragma unroll
    for (int i = 0; i < 8; i++) {
        float s = bias + v[i] * w0 + v[i + 1] * w1 + v[i + 2] * w2 + v[i + 3] * w3;
        g_xbc[(size_t)(t0 + i) * DCONVIN + c] = s / (1.f + expf(-s));
    }
}

// ---------------- softplus(dt)+dt_bias, dt*A, per-chunk inclusive cumsum ------
__global__ void dtscan_kernel(const float* __restrict__ dt_bias, const float* __restrict__ A_log)
{
    int bid = blockIdx.x;
    int c = bid >> 5, h = bid & 31;
    int s = threadIdx.x;
    int t = c * CH + s;
    float raw = g_zx[(size_t)t * DPROJ + (DINNER + DINNER + 2 * DSTATE) + h] + dt_bias[h];
    float dtv = (raw > 20.f) ? raw : log1pf(expf(raw));
    float Ah = -expf(A_log[h]);
    __shared__ float sm[CH];
    sm[s] = dtv * Ah;
    g_dt[h * SEQ + t] = dtv;
    __syncthreads();
    for (int off = 1; off < CH; off <<= 1) {
        float add = (s >= off) ? sm[s - off] : 0.f;
        __syncthreads();
        sm[s] += add;
        __syncthreads();
    }
    g_L[h * SEQ + t] = sm[s];
}

// ---------------- gram: G[c][s][j] = C_s . B_j (head-independent, NGROUPS=1) --
__global__ void __launch_bounds__(256) gram_kernel()
{
    int c = blockIdx.x;
    __shared__ float CsT[16 * 132];
    __shared__ float BsT[16 * 132];
    int tid = threadIdx.x;
    int ts = tid >> 4, tj = tid & 15;
    int base = c * CH;

    float acc[8][8];
#pragma unroll
    for (int i = 0; i < 8; i++)
#pragma unroll
        for (int k = 0; k < 8; k++) acc[i][k] = 0.f;

    for (int n0 = 0; n0 < DSTATE; n0 += 16) {
#pragma unroll
        for (int r = 0; r < 2; r++) {
            int qi = r * 256 + tid;
            int s = qi >> 2, nq = qi & 3;
            float4 vc = *(const float4*)&g_xbc[(size_t)(base + s) * DCONVIN + DINNER + DSTATE + n0 + nq * 4];
            CsT[(nq * 4 + 0) * 132 + s] = vc.x; CsT[(nq * 4 + 1) * 132 + s] = vc.y;
            CsT[(nq * 4 + 2) * 132 + s] = vc.z; CsT[(nq * 4 + 3) * 132 + s] = vc.w;
            float4 vb = *(const float4*)&g_xbc[(size_t)(base + s) * DCONVIN + DINNER + n0 + nq * 4];
            BsT[(nq * 4 + 0) * 132 + s] = vb.x; BsT[(nq * 4 + 1) * 132 + s] = vb.y;
            BsT[(nq * 4 + 2) * 132 + s] = vb.z; BsT[(nq * 4 + 3) * 132 + s] = vb.w;
        }
        __syncthreads();
#pragma unroll
        for (int nn = 0; nn < 16; nn++) {
            float4 c0 = *(float4*)&CsT[nn * 132 + ts * 8];
            float4 c1 = *(float4*)&CsT[nn * 132 + ts * 8 + 4];
            float4 b0 = *(float4*)&BsT[nn * 132 + tj * 8];
            float4 b1 = *(float4*)&BsT[nn * 132 + tj * 8 + 4];
            float cv[8] = {c0.x, c0.y, c0.z, c0.w, c1.x, c1.y, c1.z, c1.w};
            float bv[8] = {b0.x, b0.y, b0.z, b0.w, b1.x, b1.y, b1.z, b1.w};
#pragma unroll
            for (int i = 0; i < 8; i++)
#pragma unroll
                for (int k = 0; k < 8; k++) acc[i][k] += cv[i] * bv[k];
        }
        __syncthreads();
    }
#pragma unroll
    for (int i = 0; i < 8; i++) {
        size_t row = (size_t)(c * CH + ts * 8 + i) * CH;
        *(float4*)&g_Gram[row + tj * 8]     = make_float4(acc[i][0], acc[i][1], acc[i][2], acc[i][3]);
        *(float4*)&g_Gram[row + tj * 8 + 4] = make_float4(acc[i][4], acc[i][5], acc[i][6], acc[i][7]);
    }
}

// ---------------- split C block into bf16 hi/lo (for inter GEMM) --------------
__global__ void csplit_kernel()
{
    int i = blockIdx.x * 256 + threadIdx.x;   // over SEQ * 64 pairs
    if (i >= SEQ * (DSTATE / 2)) return;
    int t = i >> 6, n2 = (i & 63) * 2;
    float2 v = *(const float2*)&g_xbc[(size_t)t * DCONVIN + DINNER + DSTATE + n2];
    float h0 = bf16r(v.x), h1 = bf16r(v.y);
    g_Chi[(size_t)t * 64 + (n2 >> 1)] = packbf2(h0, h1);
    g_Clo[(size_t)t * 64 + (n2 >> 1)] = packbf2(v.x - h0, v.y - h1);
}

// ---------------- pass 1 (tensor cores): S[c,h] = (w.X)^T @ B -----------------
// Per (c,h): A[p][j] = w_j x[j][p] (M=64, K=128), B'[j][n] (N=128).
// Both operands stored K(j)-major in smem; fragments via ldmatrix.x4.trans.
// Split bf16 hi/lo, 3 mma (drop lo*lo).
#define CS_AH 0
#define CS_AL (128 * 36)            // 4608
#define CS_BH (2 * 128 * 36)        // 9216
#define CS_BL (CS_BH + 128 * 68)    // 17920
#define CS_W  (CS_BL + 128 * 68)    // 26624
#define CS_SMEM_U32 (CS_W + 128)    // 26752 u32 = 107008 B
__global__ void __launch_bounds__(128) chunkstate_mma_kernel()
{
    extern __shared__ uint32_t cs[];
    float* ws = (float*)(cs + CS_W);
    int bid = blockIdx.x;
    int c = bid >> 5, h = bid & 31;
    int tid = threadIdx.x;
    int lane = tid & 31, wid = tid >> 5;
    int base = c * CH;

    {
        float Lend = g_L[h * SEQ + base + CH - 1];
        ws[tid] = __expf(Lend - g_L[h * SEQ + base + tid]) * g_dt[h * SEQ + base + tid];
    }
    __syncthreads();

    // A tile: [j][p] bf16 pairs, row stride 36 u32
    for (int idx = tid; idx < 128 * 16; idx += 128) {
        int j = idx >> 4, p4 = (idx & 15) * 4;
        float4 v = *(const float4*)&g_xbc[(size_t)(base + j) * DCONVIN + h * HD + p4];
        float w = ws[j];
        v.x *= w; v.y *= w; v.z *= w; v.w *= w;
        float hx = bf16r(v.x), hy = bf16r(v.y), hz = bf16r(v.z), hw = bf16r(v.w);
        int o = j * 36 + (p4 >> 1);
        cs[CS_AH + o]     = packbf2(hx, hy);
        cs[CS_AH + o + 1] = packbf2(hz, hw);
        cs[CS_AL + o]     = packbf2(v.x - hx, v.y - hy);
        cs[CS_AL + o + 1] = packbf2(v.z - hz, v.w - hw);
    }
    // B tile: [j][n] bf16 pairs, row stride 68 u32
    for (int idx = tid; idx < 128 * 32; idx += 128) {
        int j = idx >> 5, n4 = (idx & 31) * 4;
        float4 v = *(const float4*)&g_xbc[(size_t)(base + j) * DCONVIN + DINNER + n4];
        float hx = bf16r(v.x), hy = bf16r(v.y), hz = bf16r(v.z), hw = bf16r(v.w);
        int o = j * 68 + (n4 >> 1);
        cs[CS_BH + o]     = packbf2(hx, hy);
        cs[CS_BH + o + 1] = packbf2(hz, hw);
        cs[CS_BL + o]     = packbf2(v.x - hx, v.y - hy);
        cs[CS_BL + o + 1] = packbf2(v.z - hz, v.w - hw);
    }
    __syncthreads();

    uint32_t sb = (uint32_t)__cvta_generic_to_shared(cs);
    // trans-load per-lane offsets (bytes):
    // A (k-major [j][p], stride 36): lanes 0-7/8-15 -> m0/m8 halves of k0-7; 16-31 -> k8-15
    const uint32_t AOFFT = (((lane & 7) + (lane >> 4) * 8) * 36 + ((lane >> 3) & 1) * 4) * 4;
    // B (k-major [j][n], stride 68): lanes 0-7/8-15 -> k0/k8 of n0-7; 16-31 -> n8-15
    const uint32_t BOFFT = (((lane & 7) + ((lane >> 3) & 1) * 8) * 68 + (lane >> 4) * 4) * 4;

    float acc[4][4][4];
#pragma unroll
    for (int mt = 0; mt < 4; mt++)
#pragma unroll
        for (int nt = 0; nt < 4; nt++)
#pragma unroll
            for (int e = 0; e < 4; e++) acc[mt][nt][e] = 0.f;

    for (int ks = 0; ks < 8; ks++) {     // k = ks*16
        uint32_t bh[4][2], bl[4][2];
#pragma unroll
        for (int np = 0; np < 2; np++) {
            uint32_t nbase = sb + (uint32_t)((ks * 16 * 68) * 4) + (uint32_t)((wid * 32 + np * 16) * 2) + BOFFT;
            ldsm4t(bh[np * 2][0], bh[np * 2][1], bh[np * 2 + 1][0], bh[np * 2 + 1][1],
                   nbase + CS_BH * 4);
            ldsm4t(bl[np * 2][0], bl[np * 2][1], bl[np * 2 + 1][0], bl[np * 2 + 1][1],
                   nbase + CS_BL * 4);
        }
#pragma unroll
        for (int mt = 0; mt < 4; mt++) {
            uint32_t abase = sb + (uint32_t)((ks * 16 * 36) * 4) + (uint32_t)((mt * 16) * 2) + AOFFT;
            uint32_t ah[4], al[4];
            ldsm4t(ah[0], ah[1], ah[2], ah[3], abase + CS_AH * 4);
            ldsm4t(al[0], al[1], al[2], al[3], abase + CS_AL * 4);
#pragma unroll
            for (int nt = 0; nt < 4; nt++) MMA_BF16(acc[mt][nt], ah, bh[nt]);
#pragma unroll
            for (int nt = 0; nt < 4; nt++) MMA_BF16(acc[mt][nt], ah, bl[nt]);
#pragma unroll
            for (int nt = 0; nt < 4; nt++) MMA_BF16(acc[mt][nt], al, bh[nt]);
        }
    }

    int g = lane >> 2, tig = lane & 3;
#pragma unroll
    for (int mt = 0; mt < 4; mt++) {
        int p = mt * 16 + g;
#pragma unroll
        for (int nt = 0; nt < 4; nt++) {
            int n = wid * 32 + nt * 8 + tig * 2;
            size_t row = ((size_t)(c * NH + h) * HD + p) * DSTATE;
            g_S[row + n]     = acc[mt][nt][0];
            g_S[row + n + 1] = acc[mt][nt][1];
            g_S[row + 8 * DSTATE + n]     = acc[mt][nt][2];
            g_S[row + 8 * DSTATE + n + 1] = acc[mt][nt][3];
        }
    }
}

// ---------------- pass 2: 32-step scan; emit H chunk-initial states as bf16 ---
__global__ void scan_kernel()
{
    int idx = blockIdx.x * 256 + threadIdx.x;   // 131072 threads, 2 n-values each
    int h = idx >> 12;
    int rem = idx & 4095;
    int p = rem >> 6;
    int n2 = (rem & 63) * 2;
    float h0 = 0.f, h1 = 0.f;
    for (int c = 0; c < NCH; c++) {
        size_t row = (size_t)c * DINNER + h * HD + p;     // Hcat row
        float b0 = bf16r(h0), b1 = bf16r(h1);
        g_Hhi[row * 64 + (n2 >> 1)] = packbf2(b0, b1);
        g_Hlo[row * 64 + (n2 >> 1)] = packbf2(h0 - b0, h1 - b1);
        float2 s = *(const float2*)&g_S[((size_t)(c * NH + h) * HD + p) * DSTATE + n2];
        float dA = expf(g_L[h * SEQ + c * CH + CH - 1]);
        h0 = dA * h0 + s.x;
        h1 = dA * h1 + s.y;
    }
}

// ---------------- pass 3: per-(chunk,head) output (intra only) ----------------
#define K5_SMEM_FLOATS 18240
__global__ void __launch_bounds__(256) chunkout_kernel(const float* __restrict__ Dvec)
{
    extern __shared__ float smdyn[];
    float* Am  = smdyn;            // 128*132 = 16896
    float* Xs  = smdyn + 16896;    // 16*68
    float* Ls  = smdyn + 17984;    // 128
    float* dts = smdyn + 18112;    // 128

    int bid = blockIdx.x;
    int c = bid >> 5, h = bid & 31;
    int tid = threadIdx.x;
    int ts = tid >> 4;
    int tj = tid & 15;
    int base = c * CH;

    if (tid < 128) {
        Ls[tid]  = g_L [h * SEQ + base + tid];
        dts[tid] = g_dt[h * SEQ + base + tid];
    }
    __syncthreads();

    const float* Gc = g_Gram + (size_t)c * CH * CH;
#pragma unroll
    for (int i = 0; i < 8; i++) {
        int s = ts * 8 + i;
        float ls = Ls[s];
        float4 g0 = *(const float4*)&Gc[(size_t)s * CH + tj * 8];
        float4 g1 = *(const float4*)&Gc[(size_t)s * CH + tj * 8 + 4];
        float gv[8] = {g0.x, g0.y, g0.z, g0.w, g1.x, g1.y, g1.z, g1.w};
#pragma unroll
        for (int k = 0; k < 8; k++) {
            int j = tj * 8 + k;
            float w = (j <= s) ? __expf(ls - Ls[j]) * dts[j] : 0.f;
            Am[s * 132 + j] = gv[k] * w;
        }
    }
    __syncthreads();

    float ai[8][4];
#pragma unroll
    for (int i = 0; i < 8; i++)
#pragma unroll
        for (int r = 0; r < 4; r++) ai[i][r] = 0.f;

    for (int k0 = 0; k0 < CH; k0 += 16) {
        {
            int j = tid >> 4, pq = tid & 15;
            float4 v = *(const float4*)&g_xbc[(size_t)(base + k0 + j) * DCONVIN + h * HD + pq * 4];
            *(float4*)&Xs[j * 68 + pq * 4] = v;
        }
        __syncthreads();
#pragma unroll
        for (int kk = 0; kk < 16; kk++) {
            float4 xv = *(float4*)&Xs[kk * 68 + tj * 4];
#pragma unroll
            for (int i = 0; i < 8; i++) {
                float am = Am[(ts * 8 + i) * 132 + k0 + kk];
                ai[i][0] += am * xv.x; ai[i][1] += am * xv.y;
                ai[i][2] += am * xv.z; ai[i][3] += am * xv.w;
            }
        }
        __syncthreads();
    }

    float Dh = Dvec[h];
#pragma unroll
    for (int i = 0; i < 8; i++) {
        int s = ts * 8 + i;
        int trow = base + s;
        float es = expf(Ls[s]);
        const float* Irow = g_Inter + ((size_t)(c * CH + s)) * DINNER + h * HD;
#pragma unroll
        for (int r = 0; r < 4; r++) {
            int p = tj * 4 + r;
            float xval = g_xbc[(size_t)trow * DCONVIN + h * HD + p];
            g_Y[(size_t)trow * DINNER + h * HD + p] = ai[i][r] + es * Irow[p] + Dh * xval;
        }
    }
}

// ---------------- RMSNorm + SiLU gate -> split bf16 ---------------------------
__global__ void normgate_kernel(const float* __restrict__ nw, const float* __restrict__ nb)
{
    int t = blockIdx.x;
    int tid = threadIdx.x;
    __shared__ float red[256];
    float ss = 0.f;
    for (int d = tid; d < DINNER; d += 256) {
        float v = g_Y[(size_t)t * DINNER + d];
        ss += v * v;
    }
    red[tid] = ss;
    __syncthreads();
    for (int off = 128; off > 0; off >>= 1) {
        if (tid < off) red[tid] += red[tid + off];
        __syncthreads();
    }
    float inv = rsqrtf(red[0] / (float)DINNER + 1e-6f);
    for (int d = tid * 2; d < DINNER; d += 512) {
        float v0 = g_Y[(size_t)t * DINNER + d];
        float v1 = g_Y[(size_t)t * DINNER + d + 1];
        float g0 = v0 * inv * nw[d] + nb[d];
        float g1 = v1 * inv * nw[d + 1] + nb[d + 1];
        float z0 = g_zx[(size_t)t * DPROJ + d];
        float z1 = g_zx[(size_t)t * DPROJ + d + 1];
        g0 *= z0 / (1.f + expf(-z0));
        g1 *= z1 / (1.f + expf(-z1));
        float h0 = bf16r(g0), h1 = bf16r(g1);
        size_t pi = ((size_t)t * DINNER + d) >> 1;
        g_Ghi[pi] = packbf2(h0, h1);
        g_Glo[pi] = packbf2(g0 - h0, g1 - h1);
    }
}

// ---------------- launch ------------------------------------------------------
extern "C" void kernel_launch(void* const* d_in, const int* in_sizes, int n_in,
                              void* d_out, int out_size)
{
    const float* u       = (const float*)d_in[0];
    const float* W_in    = (const float*)d_in[1];
    const float* conv_w  = (const float*)d_in[2];
    const float* conv_b  = (const float*)d_in[3];
    const float* W_out   = (const float*)d_in[4];
    const float* norm_w  = (const float*)d_in[5];
    const float* norm_b  = (const float*)d_in[6];
    const float* dt_bias = (const float*)d_in[7];
    const float* A_log   = (const float*)d_in[8];
    const float* Dv      = (const float*)d_in[9];
    float* out = (float*)d_out;

    float *zx, *Inter;
    uint32_t *u16, *Whi, *Wlo, *Vhi, *Vlo, *Ghi, *Glo, *Hhi, *Hlo, *Chi, *Clo;
    cudaGetSymbolAddress((void**)&zx,   g_zx);
    cudaGetSymbolAddress((void**)&Inter,g_Inter);
    cudaGetSymbolAddress((void**)&u16,  g_u16);
    cudaGetSymbolAddress((void**)&Whi,  g_Whi);
    cudaGetSymbolAddress((void**)&Wlo,  g_Wlo);
    cudaGetSymbolAddress((void**)&Vhi,  g_Vhi);
    cudaGetSymbolAddress((void**)&Vlo,  g_Vlo);
    cudaGetSymbolAddress((void**)&Ghi,  g_Ghi);
    cudaGetSymbolAddress((void**)&Glo,  g_Glo);
    cudaGetSymbolAddress((void**)&Hhi,  g_Hhi);
    cudaGetSymbolAddress((void**)&Hlo,  g_Hlo);
    cudaGetSymbolAddress((void**)&Chi,  g_Chi);
    cudaGetSymbolAddress((void**)&Clo,  g_Clo);

    const int SM1 = 23040 * 4;   // gemm<0,0,3>: 3 planes * 3 stages * 2560 u32
    const int SM2 = 20480 * 4;   // gemm<1,*,2>: 4 planes * 2 stages * 2560 u32
    const int SMC = CS_SMEM_U32 * 4;
    cudaFuncSetAttribute(gemm_bf16s_kernel<0, 0, 3>, cudaFuncAttributeMaxDynamicSharedMemorySize, SM1);
    cudaFuncSetAttribute(gemm_bf16s_kernel<1, 0, 2>, cudaFuncAttributeMaxDynamicSharedMemorySize, SM2);
    cudaFuncSetAttribute(gemm_bf16s_kernel<1, 1, 2>, cudaFuncAttributeMaxDynamicSharedMemorySize, SM2);
    cudaFuncSetAttribute(chunkstate_mma_kernel, cudaFuncAttributeMaxDynamicSharedMemorySize, SMC);
    cudaFuncSetAttribute(chunkout_kernel, cudaFuncAttributeMaxDynamicSharedMemorySize, K5_SMEM_FLOATS * 4);

    // 0. pre-convert operands
    {
        int np;
        np = SEQ * DMODEL / 2;
        convert_round_kernel<<<(np + 255) / 256, 256>>>(u, u16, np);
        np = DPROJ * DMODEL / 2;
        convert_split_kernel<<<(np + 255) / 256, 256>>>(W_in, Whi, Wlo, np);
        np = DMODEL * DINNER / 2;
        convert_split_kernel<<<(np + 255) / 256, 256>>>(W_out, Vhi, Vlo, np);
    }
    // 1. in_proj GEMM (3-stage single-sync pipeline, 2 mma)
    gemm_bf16s_kernel<0, 0, 3><<<dim3((DPROJ + 127) / 128, SEQ / 128), 256, SM1>>>(
        u16, nullptr, Whi, Wlo, zx, SEQ, DPROJ, DMODEL);
    // 2. causal depthwise conv + silu (8 t/thread)
    conv_silu_kernel<<<dim3((DCONVIN + 255) / 256, SEQ / 8), 256>>>(conv_w, conv_b);
    // 3. dt softplus + per-chunk cumsum
    dtscan_kernel<<<NCH * NH, CH>>>(dt_bias, A_log);
    // 3b. head-independent gram matrices
    gram_kernel<<<NCH, 256>>>();
    // 3c. split C block for inter GEMM
    csplit_kernel<<<(SEQ * (DSTATE / 2) + 255) / 256, 256>>>();
    // 4. chunk-local states (tensor cores)
    chunkstate_mma_kernel<<<NCH * NH, 128, SMC>>>();
    // 5. inter-chunk scan (emits split-bf16 H)
    scan_kernel<<<(NH * HD * (DSTATE / 2)) / 256, 256>>>();
    // 5b. inter term: per chunk, Inter[c] = C[c] @ Hcat[c]^T  (batched TC GEMM)
    gemm_bf16s_kernel<1, 1, 2><<<dim3(DINNER / 128, 1, NCH), 256, SM2>>>(
        Chi, Clo, Hhi, Hlo, Inter, CH, DINNER, DSTATE);
    // 6. per-chunk output (intra + inter-combine + skip)
    chunkout_kernel<<<NCH * NH, 256, K5_SMEM_FLOATS * 4>>>(Dv);
    // 7. RMSNorm + gate -> split bf16
    normgate_kernel<<<SEQ, 256>>>(norm_w, norm_b);
    // 8. out_proj GEMM (2-stage, 3 mma)
    gemm_bf16s_kernel<1, 0, 2><<<dim3(DMODEL / 128, SEQ / 128), 256, SM2>>>(
        Ghi, Glo, Vhi, Vlo, out, SEQ, DMODEL, DINNER);
}